// round 5
// baseline (speedup 1.0000x reference)
#include <cuda_runtime.h>

// Problem constants
#define NR 20000   // readings
#define NS 5000    // skills
#define DD 512     // embedding dim
#define NL 3       // layers
#define COL_CHUNKS 16

// ---------------------------------------------------------------------------
// Scratch (no cudaMalloc allowed): ~205 MB of __device__ globals
// ---------------------------------------------------------------------------
__device__ float g_invdeg_r[NR];
__device__ float g_invdeg_s[NS];
__device__ float g_colpart[COL_CHUNKS * NS];
__device__ float g_gs[NS * DD];   // h_s @ Ws[l]
__device__ float g_ts[NS * DD];   // h_s @ Vs[l]
__device__ float g_tr[NR * DD];   // h_r @ Wr[l]
__device__ float g_gr[NR * DD];   // h_r @ Vr[l]
__device__ float g_hrA[NR * DD];  // h_r ping
__device__ float g_hrB[NR * DD];  // h_r pong
__device__ float g_hsA[NS * DD];  // h_s ping
__device__ float g_hsB[NS * DD];  // h_s pong

// ---------------------------------------------------------------------------
// Degree kernels
// ---------------------------------------------------------------------------
// invdeg_r[r] = 1 / (sum_s A[r,s] + 1e-6). One block per row, float4 loads.
__global__ void rowsum_inv_k(const float* __restrict__ A, float* __restrict__ invdeg)
{
    int r = blockIdx.x;
    const float4* row = reinterpret_cast<const float4*>(A + (size_t)r * NS);
    float acc = 0.f;
    for (int c = threadIdx.x; c < NS / 4; c += blockDim.x) {
        float4 v = row[c];
        acc += (v.x + v.y) + (v.z + v.w);
    }
    #pragma unroll
    for (int off = 16; off; off >>= 1) acc += __shfl_down_sync(0xffffffffu, acc, off);
    __shared__ float ws[4];
    if ((threadIdx.x & 31) == 0) ws[threadIdx.x >> 5] = acc;
    __syncthreads();
    if (threadIdx.x == 0)
        invdeg[r] = 1.f / ((ws[0] + ws[1]) + (ws[2] + ws[3]) + 1e-6f);
}

// Column sums split over COL_CHUNKS row-chunks for parallelism (coalesced).
__global__ void colsum_part_k(const float* __restrict__ A, float* __restrict__ part)
{
    int s = blockIdx.x * blockDim.x + threadIdx.x;
    if (s >= NS) return;
    int chunk = blockIdx.y;
    const int rows = NR / COL_CHUNKS;
    const float* p = A + (size_t)(chunk * rows) * NS + s;
    float acc = 0.f;
    for (int r = 0; r < rows; r++) acc += p[(size_t)r * NS];
    part[chunk * NS + s] = acc;
}

__global__ void colsum_fin_k(const float* __restrict__ part, float* __restrict__ invdeg)
{
    int s = blockIdx.x * blockDim.x + threadIdx.x;
    if (s >= NS) return;
    float acc = 0.f;
    #pragma unroll
    for (int c = 0; c < COL_CHUNKS; c++) acc += part[c * NS + s];
    invdeg[s] = 1.f / (acc + 1e-6f);
}

// ---------------------------------------------------------------------------
// SGEMM: C[M,N] = op(A)[M,K] @ B[K,N]
//   TRANS_A = 0: A is [M,K] row-major (row stride lda)
//   TRANS_A = 1: op(A)=A_phys^T, A_phys is [K,M] row-major (row stride lda)
//   EPI = 0: C = acc
//   EPI = 2: C = relu(rowscale[m] * acc + addend[m,n])
// 128x128 tile, BK=8, 256 threads, 8x8 per-thread register tile.
// Requires: N % 128 == 0, K % 8 == 0 (true for all call sites). M guarded.
// ---------------------------------------------------------------------------
template <int TRANS_A, int EPI>
__global__ __launch_bounds__(256, 2)
void sgemm_k(int M, int N, int K, int lda,
             const float* __restrict__ A,
             const float* __restrict__ B,
             float* __restrict__ C,
             const float* __restrict__ rowscale,
             const float* __restrict__ addend)
{
    __shared__ float As[8][128];
    __shared__ float Bs[8][128];

    const int tid = threadIdx.x;
    const int bm  = blockIdx.y * 128;
    const int bn  = blockIdx.x * 128;
    const int tr  = tid >> 4;   // 0..15
    const int tc  = tid & 15;   // 0..15

    // loader indices: 8x128 tile = 256 float4, one per thread
    const int ldRow = tid >> 5;          // 0..7   (k within tile)
    const int ldCol = (tid & 31) << 2;   // 0..124 (col within tile)
    // A normal-orientation loader: 128x8 tile, one float4 per thread
    const int aRow = tid >> 1;           // 0..127 (m within tile)
    const int aCol = (tid & 1) << 2;     // 0 or 4 (k within tile)

    float acc[8][8];
    #pragma unroll
    for (int i = 0; i < 8; i++)
        #pragma unroll
        for (int j = 0; j < 8; j++) acc[i][j] = 0.f;

    for (int k0 = 0; k0 < K; k0 += 8) {
        // ---- B tile: [8][128], fully in-bounds (N%128==0, K%8==0) ----
        float4 bv = *reinterpret_cast<const float4*>(
            B + (size_t)(k0 + ldRow) * N + bn + ldCol);
        *reinterpret_cast<float4*>(&Bs[ldRow][ldCol]) = bv;

        // ---- A tile into As[k][m] ----
        if (TRANS_A) {
            int m = bm + ldCol;
            const float* p = A + (size_t)(k0 + ldRow) * lda + m;
            float4 av;
            if (m + 3 < M) {
                av = *reinterpret_cast<const float4*>(p);
            } else {
                av.x = (m + 0 < M) ? p[0] : 0.f;
                av.y = (m + 1 < M) ? p[1] : 0.f;
                av.z = (m + 2 < M) ? p[2] : 0.f;
                av.w = (m + 3 < M) ? p[3] : 0.f;
            }
            *reinterpret_cast<float4*>(&As[ldRow][ldCol]) = av;
        } else {
            int m = bm + aRow;
            float4 av = make_float4(0.f, 0.f, 0.f, 0.f);
            if (m < M)
                av = *reinterpret_cast<const float4*>(
                    A + (size_t)m * lda + k0 + aCol);
            As[aCol + 0][aRow] = av.x;
            As[aCol + 1][aRow] = av.y;
            As[aCol + 2][aRow] = av.z;
            As[aCol + 3][aRow] = av.w;
        }
        __syncthreads();

        #pragma unroll
        for (int kk = 0; kk < 8; kk++) {
            float a[8], b[8];
            #pragma unroll
            for (int i = 0; i < 8; i++) a[i] = As[kk][tr * 8 + i];
            #pragma unroll
            for (int j = 0; j < 8; j++) b[j] = Bs[kk][tc * 8 + j];
            #pragma unroll
            for (int i = 0; i < 8; i++)
                #pragma unroll
                for (int j = 0; j < 8; j++)
                    acc[i][j] = fmaf(a[i], b[j], acc[i][j]);
        }
        __syncthreads();
    }

    // ---- epilogue ----
    #pragma unroll
    for (int i = 0; i < 8; i++) {
        int m = bm + tr * 8 + i;
        if (m >= M) continue;
        float sc = 1.f;
        if (EPI == 2) sc = rowscale[m];
        #pragma unroll
        for (int j = 0; j < 8; j += 4) {
            int n = bn + tc * 8 + j;
            float4 o;
            if (EPI == 2) {
                float4 ad = *reinterpret_cast<const float4*>(
                    addend + (size_t)m * N + n);
                o.x = fmaxf(fmaf(sc, acc[i][j + 0], ad.x), 0.f);
                o.y = fmaxf(fmaf(sc, acc[i][j + 1], ad.y), 0.f);
                o.z = fmaxf(fmaf(sc, acc[i][j + 2], ad.z), 0.f);
                o.w = fmaxf(fmaf(sc, acc[i][j + 3], ad.w), 0.f);
            } else {
                o.x = acc[i][j + 0];
                o.y = acc[i][j + 1];
                o.z = acc[i][j + 2];
                o.w = acc[i][j + 3];
            }
            *reinterpret_cast<float4*>(C + (size_t)m * N + n) = o;
        }
    }
}

template <int TA, int EPI>
static inline void launch_gemm(int M, int N, int K, int lda,
                               const float* A, const float* B, float* C,
                               const float* rs, const float* add)
{
    dim3 grid(N / 128, (M + 127) / 128);
    sgemm_k<TA, EPI><<<grid, 256>>>(M, N, K, lda, A, B, C, rs, add);
}

// ---------------------------------------------------------------------------
// kernel_launch
//
// Per layer l (using: diag(d)·A·X·W == diag(d)·(A·(X·W))):
//   g_s  = h_s @ Ws[l]                                  (small GEMM)
//   t_r  = h_r @ Wr[l]                                  (small GEMM)
//   h_r' = relu( invdeg_r ⊙ (A @ g_s) + t_r )           (big GEMM, fused epi)
//   [skip below on last layer — h_s' is dead]
//   g_r  = h_r @ Vr[l]                                  (small GEMM)
//   t_s  = h_s @ Vs[l]                                  (small GEMM)
//   h_s' = relu( invdeg_s ⊙ (A^T @ g_r) + t_s )         (big GEMM^T, fused epi)
// ---------------------------------------------------------------------------
extern "C" void kernel_launch(void* const* d_in, const int* in_sizes, int n_in,
                              void* d_out, int out_size)
{
    const float* h_s_in = (const float*)d_in[0];  // [NS, DD]
    const float* A      = (const float*)d_in[1];  // [NR, NS]
    const float* r_emb  = (const float*)d_in[2];  // [NR, DD]
    const float* Wr     = (const float*)d_in[3];  // [NL, DD, DD]
    const float* Ws     = (const float*)d_in[4];
    const float* Vr     = (const float*)d_in[5];
    const float* Vs     = (const float*)d_in[6];
    float* out = (float*)d_out;                   // [NR, DD]

    float *invdr, *invds, *colpart, *gs, *ts, *tr, *gr, *hrA, *hrB, *hsA, *hsB;
    cudaGetSymbolAddress((void**)&invdr,   g_invdeg_r);
    cudaGetSymbolAddress((void**)&invds,   g_invdeg_s);
    cudaGetSymbolAddress((void**)&colpart, g_colpart);
    cudaGetSymbolAddress((void**)&gs,      g_gs);
    cudaGetSymbolAddress((void**)&ts,      g_ts);
    cudaGetSymbolAddress((void**)&tr,      g_tr);
    cudaGetSymbolAddress((void**)&gr,      g_gr);
    cudaGetSymbolAddress((void**)&hrA,     g_hrA);
    cudaGetSymbolAddress((void**)&hrB,     g_hrB);
    cudaGetSymbolAddress((void**)&hsA,     g_hsA);
    cudaGetSymbolAddress((void**)&hsB,     g_hsB);

    // degrees (once)
    rowsum_inv_k<<<NR, 128>>>(A, invdr);
    colsum_part_k<<<dim3((NS + 255) / 256, COL_CHUNKS), 256>>>(A, colpart);
    colsum_fin_k<<<(NS + 255) / 256, 256>>>(colpart, invds);

    const float* hr_in = r_emb;
    const float* hs_in = h_s_in;
    float* hr_out_bufs[NL] = { hrA, hrB, out };
    float* hs_out_bufs[2]  = { hsA, hsB };

    for (int l = 0; l < NL; l++) {
        const float* Wrl = Wr + (size_t)l * DD * DD;
        const float* Wsl = Ws + (size_t)l * DD * DD;
        const float* Vrl = Vr + (size_t)l * DD * DD;
        const float* Vsl = Vs + (size_t)l * DD * DD;

        // g_s = h_s @ Ws[l]
        launch_gemm<0, 0>(NS, DD, DD, DD, hs_in, Wsl, gs, nullptr, nullptr);
        // t_r = h_r @ Wr[l]
        launch_gemm<0, 0>(NR, DD, DD, DD, hr_in, Wrl, tr, nullptr, nullptr);
        // h_r' = relu(invdeg_r * (A @ g_s) + t_r)
        float* hr_out = hr_out_bufs[l];
        launch_gemm<0, 2>(NR, DD, NS, NS, A, gs, hr_out, invdr, tr);

        if (l < NL - 1) {
            // g_r = h_r @ Vr[l]
            launch_gemm<0, 0>(NR, DD, DD, DD, hr_in, Vrl, gr, nullptr, nullptr);
            // t_s = h_s @ Vs[l]
            launch_gemm<0, 0>(NS, DD, DD, DD, hs_in, Vsl, ts, nullptr, nullptr);
            // h_s' = relu(invdeg_s * (A^T @ g_r) + t_s)
            float* hs_out = hs_out_bufs[l];
            launch_gemm<1, 2>(NS, DD, NR, NS, A, gr, hs_out, invds, ts);
            hs_in = hs_out;
        }
        hr_in = hr_out;
    }
}

// round 7
// speedup vs baseline: 1.8347x; 1.8347x over previous
#include <cuda_runtime.h>
#include <cuda_fp16.h>
#include <cstdint>

// ---------------------------------------------------------------------------
// Problem constants
// ---------------------------------------------------------------------------
#define NR 20000          // readings
#define NS 5000           // skills
#define DD 512            // embedding dim
#define NL 3              // layers
#define NR_P 20096        // NR padded to 128
#define NS_P 5120         // NS padded to 128 (and /32)
#define KR_P 20032        // NR padded to 32/64 for K dim
#define COL_CHUNKS 16

#define STAGE_BYTES 32768                 // Ahi,Alo,Bhi,Blo tiles (8KB each)
#define HM_SMEM (3 * STAGE_BYTES)         // 98304 B dynamic smem (3 stages)

// ---------------------------------------------------------------------------
// Device scratch (no cudaMalloc allowed)
// ---------------------------------------------------------------------------
__device__ float g_invdeg_r[NR];
__device__ float g_invdeg_s[NS];
__device__ float g_colpart[COL_CHUNKS * NS];

__device__ __align__(16) __half g_Ahi[(size_t)NR_P * NS_P];
__device__ __align__(16) __half g_Alo[(size_t)NR_P * NS_P];
__device__ __align__(16) __half g_AThi[(size_t)NS_P * KR_P];
__device__ __align__(16) __half g_ATlo[(size_t)NS_P * KR_P];
__device__ __align__(16) __half g_hrhi[(size_t)NR_P * DD];
__device__ __align__(16) __half g_hrlo[(size_t)NR_P * DD];
__device__ __align__(16) __half g_hshi[(size_t)NS_P * DD];
__device__ __align__(16) __half g_hslo[(size_t)NS_P * DD];
__device__ __align__(16) __half g_gsThi[(size_t)DD * NS_P];
__device__ __align__(16) __half g_gsTlo[(size_t)DD * NS_P];
__device__ __align__(16) __half g_grThi[(size_t)DD * KR_P];
__device__ __align__(16) __half g_grTlo[(size_t)DD * KR_P];
__device__ __align__(16) __half g_WThi[DD * DD];
__device__ __align__(16) __half g_WTlo[DD * DD];

__device__ float g_gs[(size_t)NS * DD];
__device__ float g_ts[(size_t)NS * DD];
__device__ float g_tr[(size_t)NR * DD];
__device__ float g_gr[(size_t)NR * DD];
__device__ float g_hr1[(size_t)NR * DD];
__device__ float g_hr2[(size_t)NR * DD];
__device__ float g_hs1[(size_t)NS * DD];
__device__ float g_hs2[(size_t)NS * DD];

// ---------------------------------------------------------------------------
// PTX helpers (Ampere-era ISA only: compiles for plain compute_103 target)
// ---------------------------------------------------------------------------
__device__ __forceinline__ uint32_t smem_u32(const void* p) {
    uint32_t a;
    asm("{ .reg .u64 t; cvta.to.shared.u64 t, %1; cvt.u32.u64 %0, t; }"
        : "=r"(a) : "l"(p));
    return a;
}

__device__ __forceinline__ void cp16(uint32_t dst, const void* src) {
    asm volatile("cp.async.cg.shared.global [%0], [%1], 16;"
                 :: "r"(dst), "l"(src) : "memory");
}
__device__ __forceinline__ void cp_commit() {
    asm volatile("cp.async.commit_group;" ::: "memory");
}
__device__ __forceinline__ void cp_wait1() {
    asm volatile("cp.async.wait_group 1;" ::: "memory");
}

__device__ __forceinline__ void ldsm4(uint32_t& r0, uint32_t& r1,
                                      uint32_t& r2, uint32_t& r3, uint32_t a) {
    asm volatile("ldmatrix.sync.aligned.m8n8.x4.shared.b16 {%0,%1,%2,%3}, [%4];"
                 : "=r"(r0), "=r"(r1), "=r"(r2), "=r"(r3) : "r"(a));
}

__device__ __forceinline__ void mma16816(float* d, const uint32_t* a,
                                         const uint32_t* b) {
    asm volatile(
        "mma.sync.aligned.m16n8k16.row.col.f32.f16.f16.f32 "
        "{%0,%1,%2,%3}, {%4,%5,%6,%7}, {%8,%9}, {%0,%1,%2,%3};"
        : "+f"(d[0]), "+f"(d[1]), "+f"(d[2]), "+f"(d[3])
        : "r"(a[0]), "r"(a[1]), "r"(a[2]), "r"(a[3]), "r"(b[0]), "r"(b[1]));
}

// Tile layout (8KB = 128 rows x 64B): 4 segments of 2KB (one per 16B k-chunk),
// within a segment: 128B row = (r>>3), slot = (r + 2*c16) & 7. Conflict-free
// for both cp.async stores and ldmatrix row reads.
__device__ __forceinline__ uint32_t swz(int r, int c16) {
    return (uint32_t)((c16 << 11) + ((r >> 3) << 7) + (((r + 2 * c16) & 7) << 4));
}

// ---------------------------------------------------------------------------
// Stage loader: Ahi(+0) Alo(+8K) Bhi(+16K) Blo(+24K), each 128x32 fp16.
// All sources zero-padded -> no guards. 8 x 16B cp.async per thread.
// ---------------------------------------------------------------------------
__device__ __forceinline__ void load_stage(uint32_t smb, int stage,
    const __half* __restrict__ Ahi, const __half* __restrict__ Alo,
    int lda, int bm,
    const __half* __restrict__ Bhi, const __half* __restrict__ Blo,
    int ldb, int bn, int k0, int tid)
{
    const uint32_t sb = smb + stage * STAGE_BYTES;
    #pragma unroll
    for (int i = 0; i < 2; i++) {
        const int idx = tid + i * 256;
        const int c16 = idx & 3;
        const int r   = idx >> 2;
        const uint32_t so = swz(r, c16);
        const size_t aoff = (size_t)(bm + r) * lda + k0 + c16 * 8;
        const size_t boff = (size_t)(bn + r) * ldb + k0 + c16 * 8;
        cp16(sb + so,         Ahi + aoff);
        cp16(sb + 8192 + so,  Alo + aoff);
        cp16(sb + 16384 + so, Bhi + boff);
        cp16(sb + 24576 + so, Blo + boff);
    }
}

// ---------------------------------------------------------------------------
// HMMA GEMM: C[M,512] = (Ahi+Alo)[M,K] @ (Bhi+Blo)[K,512]
//   A given [M][K] row-major (padded), B given as [512][K] (i.e. B^T rows).
//   fp16 split product: hi*hi + hi*lo + lo*hi, fp32 accumulate.
//   CTA 128x128, BK=32, 3-stage cp.async, 8 warps (4M x 2N), warp 32x64.
//   EPI=0: C = acc ; EPI=2: C = relu(rowscale[m]*acc + addend[m,n])
// ---------------------------------------------------------------------------
template <int EPI>
__global__ void __launch_bounds__(256, 1)
hmma_gemm_k(int M, int Kc,
            const __half* __restrict__ Ahi, const __half* __restrict__ Alo,
            int lda,
            const __half* __restrict__ Bhi, const __half* __restrict__ Blo,
            int ldb,
            float* __restrict__ C,
            const float* __restrict__ rowscale,
            const float* __restrict__ addend)
{
    extern __shared__ char sm[];
    const uint32_t smb = smem_u32(sm);
    const int tid  = threadIdx.x;
    const int wid  = tid >> 5;
    const int lane = tid & 31;
    const int warp_m = wid & 3;   // 0..3
    const int warp_n = wid >> 2;  // 0..1
    const int bm = blockIdx.y * 128;
    const int bn = blockIdx.x * 128;

    float acc[2][8][4];
    #pragma unroll
    for (int mt = 0; mt < 2; mt++)
        #pragma unroll
        for (int nt = 0; nt < 8; nt++)
            #pragma unroll
            for (int i = 0; i < 4; i++) acc[mt][nt][i] = 0.f;

    // prefetch 2 stages
    load_stage(smb, 0, Ahi, Alo, lda, bm, Bhi, Blo, ldb, bn, 0, tid);
    cp_commit();
    load_stage(smb, 1, Ahi, Alo, lda, bm, Bhi, Blo, ldb, bn, 32, tid);
    cp_commit();

    // per-lane ldmatrix row/chunk indices
    const int a_r     = warp_m * 32 + (lane & 15);
    const int a_ch    = lane >> 4;                         // 0/1
    const int b_n     = warp_n * 64 + (lane & 7) + ((lane >> 4) << 3);
    const int b_ch    = (lane >> 3) & 1;                   // 0/1

    for (int c = 0; c < Kc; c++) {
        cp_wait1();
        __syncthreads();
        if (c + 2 < Kc)
            load_stage(smb, (c + 2) % 3, Ahi, Alo, lda, bm,
                       Bhi, Blo, ldb, bn, (c + 2) * 32, tid);
        cp_commit();

        const uint32_t sb = smb + (c % 3) * STAGE_BYTES;
        #pragma unroll
        for (int ks = 0; ks < 2; ks++) {
            uint32_t ah[2][4], al[2][4], bh[4][4], bl[4][4];
            #pragma unroll
            for (int mt = 0; mt < 2; mt++) {
                const uint32_t ad = sb + swz(a_r + mt * 16, ks * 2 + a_ch);
                ldsm4(ah[mt][0], ah[mt][1], ah[mt][2], ah[mt][3], ad);
                ldsm4(al[mt][0], al[mt][1], al[mt][2], al[mt][3], ad + 8192);
            }
            #pragma unroll
            for (int np = 0; np < 4; np++) {
                const uint32_t bd =
                    sb + 16384 + swz(b_n + np * 16, ks * 2 + b_ch);
                ldsm4(bh[np][0], bh[np][1], bh[np][2], bh[np][3], bd);
                ldsm4(bl[np][0], bl[np][1], bl[np][2], bl[np][3], bd + 8192);
            }
            #pragma unroll
            for (int mt = 0; mt < 2; mt++) {
                #pragma unroll
                for (int np = 0; np < 4; np++) {
                    mma16816(acc[mt][np * 2],     ah[mt], &bh[np][0]);
                    mma16816(acc[mt][np * 2 + 1], ah[mt], &bh[np][2]);
                    mma16816(acc[mt][np * 2],     ah[mt], &bl[np][0]);
                    mma16816(acc[mt][np * 2 + 1], ah[mt], &bl[np][2]);
                    mma16816(acc[mt][np * 2],     al[mt], &bh[np][0]);
                    mma16816(acc[mt][np * 2 + 1], al[mt], &bh[np][2]);
                }
            }
        }
    }

    // ---- epilogue ----
    const int row_in = lane >> 2;        // 0..7
    const int col_in = (lane & 3) * 2;   // 0,2,4,6
    #pragma unroll
    for (int mt = 0; mt < 2; mt++) {
        #pragma unroll
        for (int h2 = 0; h2 < 2; h2++) {
            const int m = bm + warp_m * 32 + mt * 16 + row_in + h2 * 8;
            if (m >= M) continue;
            float sc = 1.f;
            if (EPI == 2) sc = rowscale[m];
            #pragma unroll
            for (int nt = 0; nt < 8; nt++) {
                const int n = bn + warp_n * 64 + nt * 8 + col_in;
                float v0 = acc[mt][nt][h2 * 2 + 0];
                float v1 = acc[mt][nt][h2 * 2 + 1];
                float2 o;
                if (EPI == 2) {
                    const float2 ad = *reinterpret_cast<const float2*>(
                        addend + (size_t)m * DD + n);
                    o.x = fmaxf(fmaf(sc, v0, ad.x), 0.f);
                    o.y = fmaxf(fmaf(sc, v1, ad.y), 0.f);
                } else {
                    o.x = v0; o.y = v1;
                }
                *reinterpret_cast<float2*>(C + (size_t)m * DD + n) = o;
            }
        }
    }
}

// ---------------------------------------------------------------------------
// Conversion kernels (fp32 -> fp16 hi/lo)
// ---------------------------------------------------------------------------
__global__ void split_pad_k(const float* __restrict__ in,
                            __half* __restrict__ hi, __half* __restrict__ lo,
                            int M, int K, int KP, int total)
{
    int idx = blockIdx.x * 256 + threadIdx.x;
    if (idx >= total) return;
    int r = idx / KP, c = idx - r * KP;
    float v = (r < M && c < K) ? in[(size_t)r * K + c] : 0.f;
    __half h = __float2half_rn(v);
    hi[idx] = h;
    lo[idx] = __float2half_rn(v - __half2float(h));
}

__global__ void transpose_split_k(const float* __restrict__ in,
                                  __half* __restrict__ hi,
                                  __half* __restrict__ lo,
                                  int R, int C, int OR, int OC)
{
    __shared__ float t[32][33];
    const int r0 = blockIdx.x * 32;   // in-row / out-col base
    const int c0 = blockIdx.y * 32;   // in-col / out-row base
    const int tx = threadIdx.x, ty = threadIdx.y;
    #pragma unroll
    for (int k = 0; k < 32; k += 8) {
        int r = r0 + ty + k, c = c0 + tx;
        t[ty + k][tx] = (r < R && c < C) ? in[(size_t)r * C + c] : 0.f;
    }
    __syncthreads();
    #pragma unroll
    for (int k = 0; k < 32; k += 8) {
        int orow = c0 + ty + k, ocol = r0 + tx;
        if (orow < OR && ocol < OC) {
            float v = t[tx][ty + k];
            __half h = __float2half_rn(v);
            hi[(size_t)orow * OC + ocol] = h;
            lo[(size_t)orow * OC + ocol] = __float2half_rn(v - __half2float(h));
        }
    }
}

// ---------------------------------------------------------------------------
// Degree kernels
// ---------------------------------------------------------------------------
__global__ void rowsum_inv_k(const float* __restrict__ A, float* __restrict__ invdeg)
{
    int r = blockIdx.x;
    const float4* row = reinterpret_cast<const float4*>(A + (size_t)r * NS);
    float acc = 0.f;
    for (int c = threadIdx.x; c < NS / 4; c += blockDim.x) {
        float4 v = row[c];
        acc += (v.x + v.y) + (v.z + v.w);
    }
    #pragma unroll
    for (int off = 16; off; off >>= 1) acc += __shfl_down_sync(0xffffffffu, acc, off);
    __shared__ float ws[4];
    if ((threadIdx.x & 31) == 0) ws[threadIdx.x >> 5] = acc;
    __syncthreads();
    if (threadIdx.x == 0)
        invdeg[r] = 1.f / ((ws[0] + ws[1]) + (ws[2] + ws[3]) + 1e-6f);
}

__global__ void colsum_part_k(const float* __restrict__ A, float* __restrict__ part)
{
    int s = blockIdx.x * blockDim.x + threadIdx.x;
    if (s >= NS) return;
    int chunk = blockIdx.y;
    const int rows = NR / COL_CHUNKS;
    const float* p = A + (size_t)(chunk * rows) * NS + s;
    float acc = 0.f;
    for (int r = 0; r < rows; r++) acc += p[(size_t)r * NS];
    part[chunk * NS + s] = acc;
}

__global__ void colsum_fin_k(const float* __restrict__ part, float* __restrict__ invdeg)
{
    int s = blockIdx.x * blockDim.x + threadIdx.x;
    if (s >= NS) return;
    float acc = 0.f;
    #pragma unroll
    for (int c = 0; c < COL_CHUNKS; c++) acc += part[c * NS + s];
    invdeg[s] = 1.f / (acc + 1e-6f);
}

// ---------------------------------------------------------------------------
// Host orchestration
// ---------------------------------------------------------------------------
static inline void gemm0(int M, int Kc,
                         const __half* Ah, const __half* Al, int lda,
                         const __half* Bh, const __half* Bl, int ldb, float* C)
{
    dim3 grid(4, (M + 127) / 128);
    hmma_gemm_k<0><<<grid, 256, HM_SMEM>>>(M, Kc, Ah, Al, lda, Bh, Bl, ldb,
                                           C, nullptr, nullptr);
}
static inline void gemm2(int M, int Kc,
                         const __half* Ah, const __half* Al, int lda,
                         const __half* Bh, const __half* Bl, int ldb,
                         float* C, const float* rs, const float* add)
{
    dim3 grid(4, (M + 127) / 128);
    hmma_gemm_k<2><<<grid, 256, HM_SMEM>>>(M, Kc, Ah, Al, lda, Bh, Bl, ldb,
                                           C, rs, add);
}

extern "C" void kernel_launch(void* const* d_in, const int* in_sizes, int n_in,
                              void* d_out, int out_size)
{
    const float* h_s_in = (const float*)d_in[0];  // [NS, DD]
    const float* A      = (const float*)d_in[1];  // [NR, NS]
    const float* r_emb  = (const float*)d_in[2];  // [NR, DD]
    const float* Wr     = (const float*)d_in[3];  // [NL, DD, DD]
    const float* Ws     = (const float*)d_in[4];
    const float* Vr     = (const float*)d_in[5];
    const float* Vs     = (const float*)d_in[6];
    float* out = (float*)d_out;                   // [NR, DD]

    cudaFuncSetAttribute(hmma_gemm_k<0>,
                         cudaFuncAttributeMaxDynamicSharedMemorySize, HM_SMEM);
    cudaFuncSetAttribute(hmma_gemm_k<2>,
                         cudaFuncAttributeMaxDynamicSharedMemorySize, HM_SMEM);

    float *invdr, *invds, *colpart, *gs, *ts, *tr, *gr, *hr1, *hr2, *hs1, *hs2;
    __half *Ahi, *Alo, *AThi, *ATlo, *hrhi, *hrlo, *hshi, *hslo;
    __half *gsThi, *gsTlo, *grThi, *grTlo, *WThi, *WTlo;
    cudaGetSymbolAddress((void**)&invdr,   g_invdeg_r);
    cudaGetSymbolAddress((void**)&invds,   g_invdeg_s);
    cudaGetSymbolAddress((void**)&colpart, g_colpart);
    cudaGetSymbolAddress((void**)&gs,  g_gs);
    cudaGetSymbolAddress((void**)&ts,  g_ts);
    cudaGetSymbolAddress((void**)&tr,  g_tr);
    cudaGetSymbolAddress((void**)&gr,  g_gr);
    cudaGetSymbolAddress((void**)&hr1, g_hr1);
    cudaGetSymbolAddress((void**)&hr2, g_hr2);
    cudaGetSymbolAddress((void**)&hs1, g_hs1);
    cudaGetSymbolAddress((void**)&hs2, g_hs2);
    cudaGetSymbolAddress((void**)&Ahi,  g_Ahi);
    cudaGetSymbolAddress((void**)&Alo,  g_Alo);
    cudaGetSymbolAddress((void**)&AThi, g_AThi);
    cudaGetSymbolAddress((void**)&ATlo, g_ATlo);
    cudaGetSymbolAddress((void**)&hrhi, g_hrhi);
    cudaGetSymbolAddress((void**)&hrlo, g_hrlo);
    cudaGetSymbolAddress((void**)&hshi, g_hshi);
    cudaGetSymbolAddress((void**)&hslo, g_hslo);
    cudaGetSymbolAddress((void**)&gsThi, g_gsThi);
    cudaGetSymbolAddress((void**)&gsTlo, g_gsTlo);
    cudaGetSymbolAddress((void**)&grThi, g_grThi);
    cudaGetSymbolAddress((void**)&grTlo, g_grTlo);
    cudaGetSymbolAddress((void**)&WThi, g_WThi);
    cudaGetSymbolAddress((void**)&WTlo, g_WTlo);

    // --- degrees ---
    rowsum_inv_k<<<NR, 128>>>(A, invdr);
    colsum_part_k<<<dim3((NS + 255) / 256, COL_CHUNKS), 256>>>(A, colpart);
    colsum_fin_k<<<(NS + 255) / 256, 256>>>(colpart, invds);

    // --- convert A and A^T once ---
    {
        int total = NR_P * NS_P;
        split_pad_k<<<(total + 255) / 256, 256>>>(A, Ahi, Alo, NR, NS, NS_P, total);
        transpose_split_k<<<dim3((KR_P + 31) / 32, (NS_P + 31) / 32), dim3(32, 8)>>>(
            A, AThi, ATlo, NR, NS, NS_P, KR_P);
    }
    // --- split initial embeddings ---
    {
        int total = NS_P * DD;
        split_pad_k<<<(total + 255) / 256, 256>>>(h_s_in, hshi, hslo, NS, DD, DD, total);
        total = NR_P * DD;
        split_pad_k<<<(total + 255) / 256, 256>>>(r_emb, hrhi, hrlo, NR, DD, DD, total);
    }

    float* hr_out_bufs[NL] = { hr1, hr2, out };
    float* hs_out_bufs[2]  = { hs1, hs2 };

    for (int l = 0; l < NL; l++) {
        const float* Wrl = Wr + (size_t)l * DD * DD;
        const float* Wsl = Ws + (size_t)l * DD * DD;
        const float* Vrl = Vr + (size_t)l * DD * DD;
        const float* Vsl = Vs + (size_t)l * DD * DD;
        dim3 tgrid(DD / 32, DD / 32), tblk(32, 8);

        // g_s = h_s @ Ws[l]
        transpose_split_k<<<tgrid, tblk>>>(Wsl, WThi, WTlo, DD, DD, DD, DD);
        gemm0(NS, DD / 32, hshi, hslo, DD, WThi, WTlo, DD, gs);
        // t_r = h_r @ Wr[l]
        transpose_split_k<<<tgrid, tblk>>>(Wrl, WThi, WTlo, DD, DD, DD, DD);
        gemm0(NR, DD / 32, hrhi, hrlo, DD, WThi, WTlo, DD, tr);
        // gsT (B operand for big GEMM)
        transpose_split_k<<<dim3(NS_P / 32, DD / 32), tblk>>>(
            gs, gsThi, gsTlo, NS, DD, DD, NS_P);
        // h_r' = relu(invdeg_r * (A @ g_s) + t_r)
        float* hr_out = hr_out_bufs[l];
        gemm2(NR, NS_P / 32, Ahi, Alo, NS_P, gsThi, gsTlo, NS_P,
              hr_out, invdr, tr);

        if (l < NL - 1) {
            // g_r = h_r @ Vr[l]  (current-layer h_r split)
            transpose_split_k<<<tgrid, tblk>>>(Vrl, WThi, WTlo, DD, DD, DD, DD);
            gemm0(NR, DD / 32, hrhi, hrlo, DD, WThi, WTlo, DD, gr);
            // t_s = h_s @ Vs[l]
            transpose_split_k<<<tgrid, tblk>>>(Vsl, WThi, WTlo, DD, DD, DD, DD);
            gemm0(NS, DD / 32, hshi, hslo, DD, WThi, WTlo, DD, ts);
            // grT (B operand for big GEMM^T)
            transpose_split_k<<<dim3(KR_P / 32, DD / 32), tblk>>>(
                gr, grThi, grTlo, NR, DD, DD, KR_P);
            // h_s' = relu(invdeg_s * (A^T @ g_r) + t_s)
            float* hs_out = hs_out_bufs[l];
            gemm2(NS, KR_P / 32, AThi, ATlo, KR_P, grThi, grTlo, KR_P,
                  hs_out, invds, ts);

            // splits for next layer
            int total = NS_P * DD;
            split_pad_k<<<(total + 255) / 256, 256>>>(hs_out, hshi, hslo, NS, DD, DD, total);
            total = NR_P * DD;
            split_pad_k<<<(total + 255) / 256, 256>>>(hr_out, hrhi, hrlo, NR, DD, DD, total);
        }
    }
}

// round 8
// speedup vs baseline: 2.4473x; 1.3339x over previous
#include <cuda_runtime.h>
#include <cuda_fp16.h>
#include <cstdint>

// ---------------------------------------------------------------------------
// Problem constants
// ---------------------------------------------------------------------------
#define NR 20000          // readings
#define NS 5000           // skills
#define DD 512            // embedding dim
#define NL 3              // layers
#define NR_P 20096        // NR padded to 128
#define NS_P 5120         // NS padded to 128
#define KR_P 20032        // NR padded to 32 (K dim of A^T GEMM)
#define COL_CHUNKS 16
#define KSPLIT_R 2        // split-K parts for A@gs   (grid 4*157*2 = 1256)
#define KSPLIT_S 8        // split-K parts for A^T@gr (grid 4*40*8  = 640)

#define STAGE_BYTES 32768                 // Ahi,Alo,Bhi,Blo tiles (8KB each)
#define HM_SMEM (3 * STAGE_BYTES)         // 96KB dynamic smem (3 stages)

// ---------------------------------------------------------------------------
// Device scratch (no cudaMalloc allowed)
// ---------------------------------------------------------------------------
__device__ float g_invdeg_r[NR];
__device__ float g_invdeg_s[NS];
__device__ float g_colpart[COL_CHUNKS * NS];

__device__ __align__(16) __half g_Ahi[(size_t)NR_P * NS_P];
__device__ __align__(16) __half g_Alo[(size_t)NR_P * NS_P];
__device__ __align__(16) __half g_AThi[(size_t)NS_P * KR_P];
__device__ __align__(16) __half g_ATlo[(size_t)NS_P * KR_P];
__device__ __align__(16) __half g_hrhi[(size_t)NR_P * DD];
__device__ __align__(16) __half g_hrlo[(size_t)NR_P * DD];
__device__ __align__(16) __half g_hshi[(size_t)NS_P * DD];
__device__ __align__(16) __half g_hslo[(size_t)NS_P * DD];
__device__ __align__(16) __half g_gsThi[(size_t)DD * NS_P];
__device__ __align__(16) __half g_gsTlo[(size_t)DD * NS_P];
__device__ __align__(16) __half g_grThi[(size_t)DD * KR_P];
__device__ __align__(16) __half g_grTlo[(size_t)DD * KR_P];
__device__ __align__(16) __half g_WThi[1024 * DD];   // [Wx|Vx]^T fused
__device__ __align__(16) __half g_WTlo[1024 * DD];

__device__ float g_fS[(size_t)NS * 1024];            // [gs | ts]
__device__ float g_fR[(size_t)NR * 1024];            // [tr | gr]
__device__ float g_partR[(size_t)KSPLIT_R * NR * DD];
__device__ float g_partS[(size_t)KSPLIT_S * NS * DD];
__device__ float g_hrf[(size_t)NR * DD];
__device__ float g_hsf[(size_t)NS * DD];

// ---------------------------------------------------------------------------
// PTX helpers (Ampere-era ISA: compiles for plain compute_103 target)
// ---------------------------------------------------------------------------
__device__ __forceinline__ uint32_t smem_u32(const void* p) {
    uint32_t a;
    asm("{ .reg .u64 t; cvta.to.shared.u64 t, %1; cvt.u32.u64 %0, t; }"
        : "=r"(a) : "l"(p));
    return a;
}
__device__ __forceinline__ void cp16(uint32_t dst, const void* src) {
    asm volatile("cp.async.cg.shared.global [%0], [%1], 16;"
                 :: "r"(dst), "l"(src) : "memory");
}
__device__ __forceinline__ void cp_commit() {
    asm volatile("cp.async.commit_group;" ::: "memory");
}
__device__ __forceinline__ void cp_wait1() {
    asm volatile("cp.async.wait_group 1;" ::: "memory");
}
__device__ __forceinline__ void ldsm4(uint32_t& r0, uint32_t& r1,
                                      uint32_t& r2, uint32_t& r3, uint32_t a) {
    asm volatile("ldmatrix.sync.aligned.m8n8.x4.shared.b16 {%0,%1,%2,%3}, [%4];"
                 : "=r"(r0), "=r"(r1), "=r"(r2), "=r"(r3) : "r"(a));
}
__device__ __forceinline__ void mma16816(float* d, const uint32_t* a,
                                         const uint32_t* b) {
    asm volatile(
        "mma.sync.aligned.m16n8k16.row.col.f32.f16.f16.f32 "
        "{%0,%1,%2,%3}, {%4,%5,%6,%7}, {%8,%9}, {%0,%1,%2,%3};"
        : "+f"(d[0]), "+f"(d[1]), "+f"(d[2]), "+f"(d[3])
        : "r"(a[0]), "r"(a[1]), "r"(a[2]), "r"(a[3]), "r"(b[0]), "r"(b[1]));
}
// Tile layout (8KB = 128 rows x 64B): 4 segments of 2KB (one per 16B k-chunk);
// slot rotation keeps cp.async stores and ldmatrix reads conflict-free.
__device__ __forceinline__ uint32_t swz(int r, int c16) {
    return (uint32_t)((c16 << 11) + ((r >> 3) << 7) + (((r + 2 * c16) & 7) << 4));
}

// ---------------------------------------------------------------------------
// Stage loader: Ahi(+0) Alo(+8K) Bhi(+16K) Blo(+24K), each 128x32 fp16.
// All sources zero-padded -> no guards.
// ---------------------------------------------------------------------------
__device__ __forceinline__ void load_stage(uint32_t smb, int stage,
    const __half* __restrict__ Ahi, const __half* __restrict__ Alo,
    int lda, int bm,
    const __half* __restrict__ Bhi, const __half* __restrict__ Blo,
    int ldb, int bn, int k0, int tid)
{
    const uint32_t sb = smb + stage * STAGE_BYTES;
    #pragma unroll
    for (int i = 0; i < 2; i++) {
        const int idx = tid + i * 256;
        const int c16 = idx & 3;
        const int r   = idx >> 2;
        const uint32_t so = swz(r, c16);
        const size_t aoff = (size_t)(bm + r) * lda + k0 + c16 * 8;
        const size_t boff = (size_t)(bn + r) * ldb + k0 + c16 * 8;
        cp16(sb + so,         Ahi + aoff);
        cp16(sb + 8192 + so,  Alo + aoff);
        cp16(sb + 16384 + so, Bhi + boff);
        cp16(sb + 24576 + so, Blo + boff);
    }
}

// ---------------------------------------------------------------------------
// HMMA GEMM: C[M,N] = (Ahi+Alo)[M,K] @ (Bhi+Blo)[K,N]   (B given K-major)
//   fp16 split product hi*hi + hi*lo + lo*hi, fp32 accumulate.
//   CTA 128x128, BK=32, 3-stage cp.async, 8 warps (4M x 2N).
//   Split-K over gridDim.z: part p computes K-chunks [kc0, kc0+kcn) and
//   writes plain partials to C + p*part_stride. Epilogue applied separately.
// ---------------------------------------------------------------------------
__global__ void __launch_bounds__(256, 1)
hmma_gemm_k(int M, int Kc,
            const __half* __restrict__ Ahi, const __half* __restrict__ Alo,
            int lda,
            const __half* __restrict__ Bhi, const __half* __restrict__ Blo,
            int ldb,
            float* __restrict__ C, int ldc, size_t part_stride)
{
    extern __shared__ char sm[];
    const uint32_t smb = smem_u32(sm);
    const int tid  = threadIdx.x;
    const int wid  = tid >> 5;
    const int lane = tid & 31;
    const int warp_m = wid & 3;
    const int warp_n = wid >> 2;
    const int bm = blockIdx.y * 128;
    const int bn = blockIdx.x * 128;

    // split-K range
    const int P = gridDim.z, p = blockIdx.z;
    const int kbase = Kc / P, krem = Kc - kbase * P;
    const int kc0 = p * kbase + (p < krem ? p : krem);
    const int kcn = kbase + (p < krem ? 1 : 0);
    C += part_stride * (size_t)p;

    float acc[2][8][4];
    #pragma unroll
    for (int mt = 0; mt < 2; mt++)
        #pragma unroll
        for (int nt = 0; nt < 8; nt++)
            #pragma unroll
            for (int i = 0; i < 4; i++) acc[mt][nt][i] = 0.f;

    load_stage(smb, 0, Ahi, Alo, lda, bm, Bhi, Blo, ldb, bn, kc0 * 32, tid);
    cp_commit();
    if (kcn > 1)
        load_stage(smb, 1, Ahi, Alo, lda, bm, Bhi, Blo, ldb, bn,
                   (kc0 + 1) * 32, tid);
    cp_commit();

    const int a_r  = warp_m * 32 + (lane & 15);
    const int a_ch = lane >> 4;
    const int b_n  = warp_n * 64 + (lane & 7) + ((lane >> 4) << 3);
    const int b_ch = (lane >> 3) & 1;

    for (int ci = 0; ci < kcn; ci++) {
        cp_wait1();
        __syncthreads();
        if (ci + 2 < kcn)
            load_stage(smb, (ci + 2) % 3, Ahi, Alo, lda, bm,
                       Bhi, Blo, ldb, bn, (kc0 + ci + 2) * 32, tid);
        cp_commit();

        const uint32_t sb = smb + (ci % 3) * STAGE_BYTES;
        #pragma unroll
        for (int ks = 0; ks < 2; ks++) {
            uint32_t ah[2][4], al[2][4], bh[4][4], bl[4][4];
            #pragma unroll
            for (int mt = 0; mt < 2; mt++) {
                const uint32_t ad = sb + swz(a_r + mt * 16, ks * 2 + a_ch);
                ldsm4(ah[mt][0], ah[mt][1], ah[mt][2], ah[mt][3], ad);
                ldsm4(al[mt][0], al[mt][1], al[mt][2], al[mt][3], ad + 8192);
            }
            #pragma unroll
            for (int np = 0; np < 4; np++) {
                const uint32_t bd =
                    sb + 16384 + swz(b_n + np * 16, ks * 2 + b_ch);
                ldsm4(bh[np][0], bh[np][1], bh[np][2], bh[np][3], bd);
                ldsm4(bl[np][0], bl[np][1], bl[np][2], bl[np][3], bd + 8192);
            }
            #pragma unroll
            for (int mt = 0; mt < 2; mt++) {
                #pragma unroll
                for (int np = 0; np < 4; np++) {
                    mma16816(acc[mt][np * 2],     ah[mt], &bh[np][0]);
                    mma16816(acc[mt][np * 2 + 1], ah[mt], &bh[np][2]);
                    mma16816(acc[mt][np * 2],     ah[mt], &bl[np][0]);
                    mma16816(acc[mt][np * 2 + 1], ah[mt], &bl[np][2]);
                    mma16816(acc[mt][np * 2],     al[mt], &bh[np][0]);
                    mma16816(acc[mt][np * 2 + 1], al[mt], &bh[np][2]);
                }
            }
        }
    }

    // plain epilogue (partials / raw results)
    const int row_in = lane >> 2;
    const int col_in = (lane & 3) * 2;
    #pragma unroll
    for (int mt = 0; mt < 2; mt++) {
        #pragma unroll
        for (int h2 = 0; h2 < 2; h2++) {
            const int m = bm + warp_m * 32 + mt * 16 + row_in + h2 * 8;
            if (m >= M) continue;
            #pragma unroll
            for (int nt = 0; nt < 8; nt++) {
                const int n = bn + warp_n * 64 + nt * 8 + col_in;
                float2 o;
                o.x = acc[mt][nt][h2 * 2 + 0];
                o.y = acc[mt][nt][h2 * 2 + 1];
                *reinterpret_cast<float2*>(C + (size_t)m * ldc + n) = o;
            }
        }
    }
}

// ---------------------------------------------------------------------------
// reduce + epilogue: out[m,n] = relu(invdeg[m] * sum_p part[p][m,n] + add[m,n])
// ---------------------------------------------------------------------------
__global__ void reduce_epi_k(int M, int P,
                             const float* __restrict__ part, size_t pstride,
                             const float* __restrict__ invdeg,
                             const float* __restrict__ add, int ld_add,
                             float* __restrict__ out)
{
    int idx = blockIdx.x * 256 + threadIdx.x;   // over M * 128 float4s
    if (idx >= M * 128) return;
    int m = idx >> 7, q = (idx & 127) << 2;
    float4 s = make_float4(0.f, 0.f, 0.f, 0.f);
    for (int pp = 0; pp < P; pp++) {
        const float4 v = *reinterpret_cast<const float4*>(
            part + pp * pstride + (size_t)m * DD + q);
        s.x += v.x; s.y += v.y; s.z += v.z; s.w += v.w;
    }
    const float sc = invdeg[m];
    const float4 a = *reinterpret_cast<const float4*>(
        add + (size_t)m * ld_add + q);
    float4 o;
    o.x = fmaxf(fmaf(sc, s.x, a.x), 0.f);
    o.y = fmaxf(fmaf(sc, s.y, a.y), 0.f);
    o.z = fmaxf(fmaf(sc, s.z, a.z), 0.f);
    o.w = fmaxf(fmaf(sc, s.w, a.w), 0.f);
    *reinterpret_cast<float4*>(out + (size_t)m * DD + q) = o;
}

// ---------------------------------------------------------------------------
// Conversions
// ---------------------------------------------------------------------------
// A [NR x 5000] fp32 -> hi/lo [NR_P x NS_P] fp16, fused with row-degree.
__global__ void split_rowsA_k(const float* __restrict__ A,
                              __half* __restrict__ hi, __half* __restrict__ lo,
                              float* __restrict__ invdeg)
{
    const int r = blockIdx.x;           // 0..NR_P-1
    const bool real = (r < NR);
    const int tid = threadIdx.x;        // 256
    float acc = 0.f;
    for (int c4 = tid; c4 < NS_P / 4; c4 += 256) {
        float4 v = make_float4(0.f, 0.f, 0.f, 0.f);
        if (real && c4 < NS / 4)
            v = *reinterpret_cast<const float4*>(A + (size_t)r * NS + c4 * 4);
        acc += (v.x + v.y) + (v.z + v.w);
        __half h0 = __float2half_rn(v.x), h1 = __float2half_rn(v.y);
        __half h2 = __float2half_rn(v.z), h3 = __float2half_rn(v.w);
        const size_t o = (size_t)r * NS_P + c4 * 4;
        *reinterpret_cast<__half2*>(hi + o)     = __halves2half2(h0, h1);
        *reinterpret_cast<__half2*>(hi + o + 2) = __halves2half2(h2, h3);
        *reinterpret_cast<__half2*>(lo + o) = __halves2half2(
            __float2half_rn(v.x - __half2float(h0)),
            __float2half_rn(v.y - __half2float(h1)));
        *reinterpret_cast<__half2*>(lo + o + 2) = __halves2half2(
            __float2half_rn(v.z - __half2float(h2)),
            __float2half_rn(v.w - __half2float(h3)));
    }
    #pragma unroll
    for (int off = 16; off; off >>= 1) acc += __shfl_down_sync(0xffffffffu, acc, off);
    __shared__ float ws[8];
    if ((tid & 31) == 0) ws[tid >> 5] = acc;
    __syncthreads();
    if (tid == 0 && real) {
        float s = 0.f;
        #pragma unroll
        for (int w = 0; w < 8; w++) s += ws[w];
        invdeg[r] = 1.f / (s + 1e-6f);
    }
}

// h [M x 512] fp32 -> hi/lo [MP x 512] fp16 (grid = MP blocks, 128 threads)
__global__ void split_rows_k(const float* __restrict__ in,
                             __half* __restrict__ hi, __half* __restrict__ lo,
                             int M)
{
    const int r = blockIdx.x;
    const int c = threadIdx.x * 4;
    float4 v = make_float4(0.f, 0.f, 0.f, 0.f);
    if (r < M)
        v = *reinterpret_cast<const float4*>(in + (size_t)r * DD + c);
    __half h0 = __float2half_rn(v.x), h1 = __float2half_rn(v.y);
    __half h2 = __float2half_rn(v.z), h3 = __float2half_rn(v.w);
    const size_t o = (size_t)r * DD + c;
    *reinterpret_cast<__half2*>(hi + o)     = __halves2half2(h0, h1);
    *reinterpret_cast<__half2*>(hi + o + 2) = __halves2half2(h2, h3);
    *reinterpret_cast<__half2*>(lo + o) = __halves2half2(
        __float2half_rn(v.x - __half2float(h0)),
        __float2half_rn(v.y - __half2float(h1)));
    *reinterpret_cast<__half2*>(lo + o + 2) = __halves2half2(
        __float2half_rn(v.z - __half2float(h2)),
        __float2half_rn(v.w - __half2float(h3)));
}

// fp32 [R x C] (row stride ld_in) -> transposed fp16 hi/lo [OR x OC], zero-pad
__global__ void transpose_split_k(const float* __restrict__ in, int ld_in,
                                  __half* __restrict__ hi,
                                  __half* __restrict__ lo,
                                  int R, int C, int OR, int OC)
{
    __shared__ float t[32][33];
    const int r0 = blockIdx.x * 32;   // in-row / out-col base
    const int c0 = blockIdx.y * 32;   // in-col / out-row base
    const int tx = threadIdx.x, ty = threadIdx.y;
    #pragma unroll
    for (int k = 0; k < 32; k += 8) {
        int r = r0 + ty + k, c = c0 + tx;
        t[ty + k][tx] = (r < R && c < C) ? in[(size_t)r * ld_in + c] : 0.f;
    }
    __syncthreads();
    #pragma unroll
    for (int k = 0; k < 32; k += 8) {
        int orow = c0 + ty + k, ocol = r0 + tx;
        if (orow < OR && ocol < OC) {
            float v = t[tx][ty + k];
            __half h = __float2half_rn(v);
            hi[(size_t)orow * OC + ocol] = h;
            lo[(size_t)orow * OC + ocol] = __float2half_rn(v - __half2float(h));
        }
    }
}

// ---------------------------------------------------------------------------
// Column-degree kernels
// ---------------------------------------------------------------------------
__global__ void colsum_part_k(const float* __restrict__ A, float* __restrict__ part)
{
    int s = blockIdx.x * blockDim.x + threadIdx.x;
    if (s >= NS) return;
    int chunk = blockIdx.y;
    const int rows = NR / COL_CHUNKS;
    const float* p = A + (size_t)(chunk * rows) * NS + s;
    float acc = 0.f;
    for (int r = 0; r < rows; r++) acc += p[(size_t)r * NS];
    part[chunk * NS + s] = acc;
}
__global__ void colsum_fin_k(const float* __restrict__ part, float* __restrict__ invdeg)
{
    int s = blockIdx.x * blockDim.x + threadIdx.x;
    if (s >= NS) return;
    float acc = 0.f;
    #pragma unroll
    for (int c = 0; c < COL_CHUNKS; c++) acc += part[c * NS + s];
    invdeg[s] = 1.f / (acc + 1e-6f);
}

// ---------------------------------------------------------------------------
// Host orchestration
// ---------------------------------------------------------------------------
extern "C" void kernel_launch(void* const* d_in, const int* in_sizes, int n_in,
                              void* d_out, int out_size)
{
    const float* h_s_in = (const float*)d_in[0];  // [NS, DD]
    const float* A      = (const float*)d_in[1];  // [NR, NS]
    const float* r_emb  = (const float*)d_in[2];  // [NR, DD]
    const float* Wr     = (const float*)d_in[3];  // [NL, DD, DD]
    const float* Ws     = (const float*)d_in[4];
    const float* Vr     = (const float*)d_in[5];
    const float* Vs     = (const float*)d_in[6];
    float* out = (float*)d_out;                   // [NR, DD]

    cudaFuncSetAttribute(hmma_gemm_k,
                         cudaFuncAttributeMaxDynamicSharedMemorySize, HM_SMEM);

    float *invdr, *invds, *colpart, *fS, *fR, *partR, *partS, *hrf, *hsf;
    __half *Ahi, *Alo, *AThi, *ATlo, *hrhi, *hrlo, *hshi, *hslo;
    __half *gsThi, *gsTlo, *grThi, *grTlo, *WThi, *WTlo;
    cudaGetSymbolAddress((void**)&invdr,   g_invdeg_r);
    cudaGetSymbolAddress((void**)&invds,   g_invdeg_s);
    cudaGetSymbolAddress((void**)&colpart, g_colpart);
    cudaGetSymbolAddress((void**)&fS,    g_fS);
    cudaGetSymbolAddress((void**)&fR,    g_fR);
    cudaGetSymbolAddress((void**)&partR, g_partR);
    cudaGetSymbolAddress((void**)&partS, g_partS);
    cudaGetSymbolAddress((void**)&hrf,   g_hrf);
    cudaGetSymbolAddress((void**)&hsf,   g_hsf);
    cudaGetSymbolAddress((void**)&Ahi,  g_Ahi);
    cudaGetSymbolAddress((void**)&Alo,  g_Alo);
    cudaGetSymbolAddress((void**)&AThi, g_AThi);
    cudaGetSymbolAddress((void**)&ATlo, g_ATlo);
    cudaGetSymbolAddress((void**)&hrhi, g_hrhi);
    cudaGetSymbolAddress((void**)&hrlo, g_hrlo);
    cudaGetSymbolAddress((void**)&hshi, g_hshi);
    cudaGetSymbolAddress((void**)&hslo, g_hslo);
    cudaGetSymbolAddress((void**)&gsThi, g_gsThi);
    cudaGetSymbolAddress((void**)&gsTlo, g_gsTlo);
    cudaGetSymbolAddress((void**)&grThi, g_grThi);
    cudaGetSymbolAddress((void**)&grTlo, g_grTlo);
    cudaGetSymbolAddress((void**)&WThi, g_WThi);
    cudaGetSymbolAddress((void**)&WTlo, g_WTlo);

    const dim3 tblk(32, 8);

    // --- A split (fused with row degrees), A^T split, column degrees ---
    split_rowsA_k<<<NR_P, 256>>>(A, Ahi, Alo, invdr);
    transpose_split_k<<<dim3(KR_P / 32, NS_P / 32), tblk>>>(
        A, NS, AThi, ATlo, NR, NS, NS_P, KR_P);
    colsum_part_k<<<dim3((NS + 255) / 256, COL_CHUNKS), 256>>>(A, colpart);
    colsum_fin_k<<<(NS + 255) / 256, 256>>>(colpart, invds);

    // --- initial embedding splits ---
    split_rows_k<<<NS_P, 128>>>(h_s_in, hshi, hslo, NS);
    split_rows_k<<<NR_P, 128>>>(r_emb, hrhi, hrlo, NR);

    for (int l = 0; l < NL; l++) {
        const float* Wrl = Wr + (size_t)l * DD * DD;
        const float* Wsl = Ws + (size_t)l * DD * DD;
        const float* Vrl = Vr + (size_t)l * DD * DD;
        const float* Vsl = Vs + (size_t)l * DD * DD;
        const bool last = (l == NL - 1);
        const int NW = last ? 512 : 1024;   // fused transform width
        const dim3 wgrid(16, 16);

        // ---- fused skill-side transform: fS = h_s @ [Ws | Vs] ----
        transpose_split_k<<<wgrid, tblk>>>(Wsl, DD, WThi, WTlo, DD, DD, DD, DD);
        if (!last)
            transpose_split_k<<<wgrid, tblk>>>(Vsl, DD, WThi + 512 * DD,
                                               WTlo + 512 * DD, DD, DD, DD, DD);
        hmma_gemm_k<<<dim3(NW / 128, NS_P / 128, 1), 256, HM_SMEM>>>(
            NS, DD / 32, hshi, hslo, DD, WThi, WTlo, DD, fS, 1024, 0);

        // ---- fused reading-side transform: fR = h_r @ [Wr | Vr] ----
        transpose_split_k<<<wgrid, tblk>>>(Wrl, DD, WThi, WTlo, DD, DD, DD, DD);
        if (!last)
            transpose_split_k<<<wgrid, tblk>>>(Vrl, DD, WThi + 512 * DD,
                                               WTlo + 512 * DD, DD, DD, DD, DD);
        hmma_gemm_k<<<dim3(NW / 128, NR_P / 128, 1), 256, HM_SMEM>>>(
            NR, DD / 32, hrhi, hrlo, DD, WThi, WTlo, DD, fR, 1024, 0);

        // ---- gs^T for big GEMM B operand ----
        transpose_split_k<<<dim3(NS_P / 32, DD / 32), tblk>>>(
            fS, 1024, gsThi, gsTlo, NS, DD, DD, NS_P);

        // ---- h_r' = relu(invdeg_r * (A @ gs) + tr), split-K=2 ----
        hmma_gemm_k<<<dim3(4, NR_P / 128, KSPLIT_R), 256, HM_SMEM>>>(
            NR, NS_P / 32, Ahi, Alo, NS_P, gsThi, gsTlo, NS_P,
            partR, DD, (size_t)NR * DD);
        float* hr_out = last ? out : hrf;
        reduce_epi_k<<<(NR * 128 + 255) / 256, 256>>>(
            NR, KSPLIT_R, partR, (size_t)NR * DD, invdr, fR, 1024, hr_out);

        if (!last) {
            // ---- gr^T for big GEMM^T B operand (gr = fR cols 512..1023) ----
            transpose_split_k<<<dim3(KR_P / 32, DD / 32), tblk>>>(
                fR + 512, 1024, grThi, grTlo, NR, DD, DD, KR_P);

            // ---- h_s' = relu(invdeg_s * (A^T @ gr) + ts), split-K=8 ----
            hmma_gemm_k<<<dim3(4, NS_P / 128, KSPLIT_S), 256, HM_SMEM>>>(
                NS, KR_P / 32, AThi, ATlo, KR_P, grThi, grTlo, KR_P,
                partS, DD, (size_t)NS * DD);
            reduce_epi_k<<<(NS * 128 + 255) / 256, 256>>>(
                NS, KSPLIT_S, partS, (size_t)NS * DD, invds, fS + 512, 1024, hsf);

            // ---- re-split updated embeddings for next layer ----
            split_rows_k<<<NR_P, 128>>>(hr_out, hrhi, hrlo, NR);
            split_rows_k<<<NS_P, 128>>>(hsf, hshi, hslo, NS);
        }
    }
}

// round 9
// speedup vs baseline: 4.1897x; 1.7119x over previous
#include <cuda_runtime.h>
#include <cuda_fp16.h>
#include <cstdint>

// ---------------------------------------------------------------------------
// Problem constants
// ---------------------------------------------------------------------------
#define NR 20000          // readings
#define NS 5000           // skills
#define DD 512            // embedding dim
#define NL 3              // layers
#define NR_P 20096        // NR padded to 128
#define NS_P 5120         // NS padded to 128
#define KR_P 20032        // NR padded to 32 (K dim of A^T GEMM)
#define COL_CHUNKS 16
#define KSPLIT_R 3        // split-K for A@gs   (grid 4*157*3 = 1884, 97.9%)
#define KSPLIT_S 8        // split-K for A^T@gr (grid 4*40*8  = 1280, 96.1%)

#define STAGE_BYTES 32768                 // Ahi,Alo,Bhi,Blo tiles (8KB each)
#define HM_SMEM (3 * STAGE_BYTES)         // 96KB dynamic smem (3 stages)

// ---------------------------------------------------------------------------
// Device scratch (no cudaMalloc allowed)
// ---------------------------------------------------------------------------
__device__ float g_invdeg_r[NR];
__device__ float g_invdeg_s[NS];
__device__ float g_colpart[COL_CHUNKS * NS];

__device__ __align__(16) __half g_Ahi[(size_t)NR_P * NS_P];
__device__ __align__(16) __half g_Alo[(size_t)NR_P * NS_P];
__device__ __align__(16) __half g_hrhi[(size_t)NR_P * DD];
__device__ __align__(16) __half g_hrlo[(size_t)NR_P * DD];
__device__ __align__(16) __half g_hshi[(size_t)NS_P * DD];
__device__ __align__(16) __half g_hslo[(size_t)NS_P * DD];
__device__ __align__(16) __half g_gshi[(size_t)NS_P * DD];
__device__ __align__(16) __half g_gslo[(size_t)NS_P * DD];
__device__ __align__(16) __half g_grhi[(size_t)NR_P * DD];
__device__ __align__(16) __half g_grlo[(size_t)NR_P * DD];
__device__ __align__(16) __half g_WShi[(size_t)NL * DD * 1024];  // [Ws|Vs]
__device__ __align__(16) __half g_WSlo[(size_t)NL * DD * 1024];
__device__ __align__(16) __half g_WRhi[(size_t)NL * DD * 1024];  // [Wr|Vr]
__device__ __align__(16) __half g_WRlo[(size_t)NL * DD * 1024];

__device__ float g_fS[(size_t)NS * 1024];            // [gs | ts]
__device__ float g_fR[(size_t)NR * 1024];            // [tr | gr]
__device__ float g_partR[(size_t)KSPLIT_R * NR * DD];
__device__ float g_partS[(size_t)KSPLIT_S * NS * DD];

// ---------------------------------------------------------------------------
// PTX helpers (Ampere-era ISA: compiles for plain compute_103 target)
// ---------------------------------------------------------------------------
__device__ __forceinline__ uint32_t smem_u32(const void* p) {
    uint32_t a;
    asm("{ .reg .u64 t; cvta.to.shared.u64 t, %1; cvt.u32.u64 %0, t; }"
        : "=r"(a) : "l"(p));
    return a;
}
__device__ __forceinline__ void cp16(uint32_t dst, const void* src) {
    asm volatile("cp.async.cg.shared.global [%0], [%1], 16;"
                 :: "r"(dst), "l"(src) : "memory");
}
__device__ __forceinline__ void cp_commit() {
    asm volatile("cp.async.commit_group;" ::: "memory");
}
__device__ __forceinline__ void cp_wait1() {
    asm volatile("cp.async.wait_group 1;" ::: "memory");
}
__device__ __forceinline__ void ldsm4(uint32_t& r0, uint32_t& r1,
                                      uint32_t& r2, uint32_t& r3, uint32_t a) {
    asm volatile("ldmatrix.sync.aligned.m8n8.x4.shared.b16 {%0,%1,%2,%3}, [%4];"
                 : "=r"(r0), "=r"(r1), "=r"(r2), "=r"(r3) : "r"(a));
}
__device__ __forceinline__ void ldsm4t(uint32_t& r0, uint32_t& r1,
                                       uint32_t& r2, uint32_t& r3, uint32_t a) {
    asm volatile("ldmatrix.sync.aligned.m8n8.x4.trans.shared.b16 {%0,%1,%2,%3}, [%4];"
                 : "=r"(r0), "=r"(r1), "=r"(r2), "=r"(r3) : "r"(a));
}
__device__ __forceinline__ void mma16816(float* d, const uint32_t* a,
                                         const uint32_t* b) {
    asm volatile(
        "mma.sync.aligned.m16n8k16.row.col.f32.f16.f16.f32 "
        "{%0,%1,%2,%3}, {%4,%5,%6,%7}, {%8,%9}, {%0,%1,%2,%3};"
        : "+f"(d[0]), "+f"(d[1]), "+f"(d[2]), "+f"(d[3])
        : "r"(a[0]), "r"(a[1]), "r"(a[2]), "r"(a[3]), "r"(b[0]), "r"(b[1]));
}
// A-normal tile [128m x 32k] (64B rows, 4 segments): conflict-free (R8 format)
__device__ __forceinline__ uint32_t swz(int r, int c16) {
    return (uint32_t)((c16 << 11) + ((r >> 3) << 7) + (((r + 2 * c16) & 7) << 4));
}
// K-major tile [32k x 128cols] (256B rows): XOR swizzle, conflict-free for
// cp.async stores (c varies) and ldmatrix phases (k varies within 8 lanes).
__device__ __forceinline__ uint32_t swz_kn(int r, int c) {
    return (uint32_t)(r * 256 + ((c & 8) << 4) + (((c ^ r) & 7) << 4));
}

// ---------------------------------------------------------------------------
// Stage loader. Layout per stage: Ahi(+0) Alo(+8K) Bhi(+16K) Blo(+24K).
// B always [K,N] row-major source. A: [M,K] (A_TRANS=0) or [K,M] (A_TRANS=1).
// All sources zero-padded -> no guards.
// ---------------------------------------------------------------------------
template <int A_TRANS>
__device__ __forceinline__ void load_stage(uint32_t smb, int stage,
    const __half* __restrict__ Ahi, const __half* __restrict__ Alo,
    int lda, int bm,
    const __half* __restrict__ Bhi, const __half* __restrict__ Blo,
    int ldb, int bn, int k0, int tid)
{
    const uint32_t sb = smb + stage * STAGE_BYTES;
    #pragma unroll
    for (int i = 0; i < 2; i++) {
        const int idx = tid + i * 256;
        const int r = idx >> 4, c = idx & 15;
        const uint32_t so = swz_kn(r, c);
        const size_t bo = (size_t)(k0 + r) * ldb + bn + c * 8;
        cp16(sb + 16384 + so, Bhi + bo);
        cp16(sb + 24576 + so, Blo + bo);
        if (A_TRANS) {
            const size_t ao = (size_t)(k0 + r) * lda + bm + c * 8;
            cp16(sb + so,        Ahi + ao);
            cp16(sb + 8192 + so, Alo + ao);
        } else {
            const int c16 = idx & 3, ra = idx >> 2;
            const uint32_t soA = swz(ra, c16);
            const size_t ao = (size_t)(bm + ra) * lda + k0 + c16 * 8;
            cp16(sb + soA,        Ahi + ao);
            cp16(sb + 8192 + soA, Alo + ao);
        }
    }
}

// ---------------------------------------------------------------------------
// HMMA GEMM: C[M,N] = op(Ahi+Alo)[M,K] @ (Bhi+Blo)[K,N]
//   B source is [K,N] row-major (trans ldmatrix). A_TRANS=1 reads A from
//   [K,M] row-major (i.e. computes A^T @ B with the original A buffer).
//   fp16 split product hi*hi + hi*lo + lo*hi, fp32 accumulate.
//   CTA 128x128, BK=32, 3-stage cp.async, 8 warps (4M x 2N), 2 CTAs/SM.
//   Split-K over gridDim.z -> plain partials at C + z*part_stride.
// ---------------------------------------------------------------------------
template <int A_TRANS>
__global__ void __launch_bounds__(256, 2)
hmma_gemm_k(int M, int Kc,
            const __half* __restrict__ Ahi, const __half* __restrict__ Alo,
            int lda,
            const __half* __restrict__ Bhi, const __half* __restrict__ Blo,
            int ldb,
            float* __restrict__ C, int ldc, size_t part_stride)
{
    extern __shared__ char sm[];
    const uint32_t smb = smem_u32(sm);
    const int tid  = threadIdx.x;
    const int wid  = tid >> 5;
    const int lane = tid & 31;
    const int warp_m = wid & 3;
    const int warp_n = wid >> 2;
    const int bm = blockIdx.y * 128;
    const int bn = blockIdx.x * 128;

    const int P = gridDim.z, p = blockIdx.z;
    const int kbase = Kc / P, krem = Kc - kbase * P;
    const int kc0 = p * kbase + (p < krem ? p : krem);
    const int kcn = kbase + (p < krem ? 1 : 0);
    C += part_stride * (size_t)p;

    float acc[2][8][4];
    #pragma unroll
    for (int mt = 0; mt < 2; mt++)
        #pragma unroll
        for (int nt = 0; nt < 8; nt++)
            #pragma unroll
            for (int i = 0; i < 4; i++) acc[mt][nt][i] = 0.f;

    load_stage<A_TRANS>(smb, 0, Ahi, Alo, lda, bm, Bhi, Blo, ldb, bn,
                        kc0 * 32, tid);
    cp_commit();
    if (kcn > 1)
        load_stage<A_TRANS>(smb, 1, Ahi, Alo, lda, bm, Bhi, Blo, ldb, bn,
                            (kc0 + 1) * 32, tid);
    cp_commit();

    // per-lane ldmatrix indices
    const int aN_r  = warp_m * 32 + (lane & 15);        // A normal: m row
    const int aN_ch = lane >> 4;                         // A normal: k chunk
    const int aT_r  = (lane & 7) + ((lane >> 4) << 3);   // A trans: k row off
    const int aT_cb = warp_m * 4 + ((lane >> 3) & 1);    // A trans: m chunk
    const int b_r   = lane & 15;                         // B: k row offset
    const int b_cb  = warp_n * 8 + (lane >> 4);          // B: n chunk base

    for (int ci = 0; ci < kcn; ci++) {
        cp_wait1();
        __syncthreads();
        if (ci + 2 < kcn)
            load_stage<A_TRANS>(smb, (ci + 2) % 3, Ahi, Alo, lda, bm,
                                Bhi, Blo, ldb, bn, (kc0 + ci + 2) * 32, tid);
        cp_commit();

        const uint32_t sb = smb + (ci % 3) * STAGE_BYTES;
        #pragma unroll
        for (int ks = 0; ks < 2; ks++) {
            uint32_t ah[2][4], al[2][4], bh[4][4], bl[4][4];
            #pragma unroll
            for (int mt = 0; mt < 2; mt++) {
                uint32_t ad;
                if (A_TRANS)
                    ad = sb + swz_kn(ks * 16 + aT_r, aT_cb + mt * 2);
                else
                    ad = sb + swz(aN_r + mt * 16, ks * 2 + aN_ch);
                if (A_TRANS) {
                    ldsm4t(ah[mt][0], ah[mt][1], ah[mt][2], ah[mt][3], ad);
                    ldsm4t(al[mt][0], al[mt][1], al[mt][2], al[mt][3], ad + 8192);
                } else {
                    ldsm4(ah[mt][0], ah[mt][1], ah[mt][2], ah[mt][3], ad);
                    ldsm4(al[mt][0], al[mt][1], al[mt][2], al[mt][3], ad + 8192);
                }
            }
            #pragma unroll
            for (int np = 0; np < 4; np++) {
                const uint32_t bd =
                    sb + 16384 + swz_kn(ks * 16 + b_r, b_cb + np * 2);
                ldsm4t(bh[np][0], bh[np][1], bh[np][2], bh[np][3], bd);
                ldsm4t(bl[np][0], bl[np][1], bl[np][2], bl[np][3], bd + 8192);
            }
            #pragma unroll
            for (int mt = 0; mt < 2; mt++) {
                #pragma unroll
                for (int np = 0; np < 4; np++) {
                    mma16816(acc[mt][np * 2],     ah[mt], &bh[np][0]);
                    mma16816(acc[mt][np * 2 + 1], ah[mt], &bh[np][2]);
                    mma16816(acc[mt][np * 2],     ah[mt], &bl[np][0]);
                    mma16816(acc[mt][np * 2 + 1], ah[mt], &bl[np][2]);
                    mma16816(acc[mt][np * 2],     al[mt], &bh[np][0]);
                    mma16816(acc[mt][np * 2 + 1], al[mt], &bh[np][2]);
                }
            }
        }
    }

    const int row_in = lane >> 2;
    const int col_in = (lane & 3) * 2;
    #pragma unroll
    for (int mt = 0; mt < 2; mt++) {
        #pragma unroll
        for (int h2 = 0; h2 < 2; h2++) {
            const int m = bm + warp_m * 32 + mt * 16 + row_in + h2 * 8;
            if (m >= M) continue;
            #pragma unroll
            for (int nt = 0; nt < 8; nt++) {
                const int n = bn + warp_n * 64 + nt * 8 + col_in;
                float2 o;
                o.x = acc[mt][nt][h2 * 2 + 0];
                o.y = acc[mt][nt][h2 * 2 + 1];
                *reinterpret_cast<float2*>(C + (size_t)m * ldc + n) = o;
            }
        }
    }
}

// ---------------------------------------------------------------------------
// reduce + epilogue: v = relu(invdeg[m] * sum_p part[p] + add[m,n])
//   WRITE_F32=1: write fp32 out (rows < M only). Otherwise write fp16 hi/lo
//   split, padded rows (m >= M) get zeros. Grid covers MP rows.
// ---------------------------------------------------------------------------
template <int WRITE_F32>
__global__ void reduce_epi_k(int M, int MP, int P,
                             const float* __restrict__ part, size_t pstride,
                             const float* __restrict__ invdeg,
                             const float* __restrict__ add, int ld_add,
                             float* __restrict__ out32,
                             __half* __restrict__ hi, __half* __restrict__ lo)
{
    int idx = blockIdx.x * 256 + threadIdx.x;   // over MP * 128 float4s
    if (idx >= MP * 128) return;
    int m = idx >> 7, q = (idx & 127) << 2;
    float4 o = make_float4(0.f, 0.f, 0.f, 0.f);
    if (m < M) {
        float4 s = make_float4(0.f, 0.f, 0.f, 0.f);
        for (int pp = 0; pp < P; pp++) {
            const float4 v = *reinterpret_cast<const float4*>(
                part + pp * pstride + (size_t)m * DD + q);
            s.x += v.x; s.y += v.y; s.z += v.z; s.w += v.w;
        }
        const float sc = invdeg[m];
        const float4 a = *reinterpret_cast<const float4*>(
            add + (size_t)m * ld_add + q);
        o.x = fmaxf(fmaf(sc, s.x, a.x), 0.f);
        o.y = fmaxf(fmaf(sc, s.y, a.y), 0.f);
        o.z = fmaxf(fmaf(sc, s.z, a.z), 0.f);
        o.w = fmaxf(fmaf(sc, s.w, a.w), 0.f);
    }
    if (WRITE_F32) {
        if (m < M)
            *reinterpret_cast<float4*>(out32 + (size_t)m * DD + q) = o;
    } else {
        __half h0 = __float2half_rn(o.x), h1 = __float2half_rn(o.y);
        __half h2 = __float2half_rn(o.z), h3 = __float2half_rn(o.w);
        const size_t off = (size_t)m * DD + q;
        *reinterpret_cast<__half2*>(hi + off)     = __halves2half2(h0, h1);
        *reinterpret_cast<__half2*>(hi + off + 2) = __halves2half2(h2, h3);
        *reinterpret_cast<__half2*>(lo + off) = __halves2half2(
            __float2half_rn(o.x - __half2float(h0)),
            __float2half_rn(o.y - __half2float(h1)));
        *reinterpret_cast<__half2*>(lo + off + 2) = __halves2half2(
            __float2half_rn(o.z - __half2float(h2)),
            __float2half_rn(o.w - __half2float(h3)));
    }
}

// ---------------------------------------------------------------------------
// Conversions
// ---------------------------------------------------------------------------
// A [NR x 5000] fp32 -> hi/lo [NR_P x NS_P] fp16, fused with row degrees.
__global__ void split_rowsA_k(const float* __restrict__ A,
                              __half* __restrict__ hi, __half* __restrict__ lo,
                              float* __restrict__ invdeg)
{
    const int r = blockIdx.x;           // 0..NR_P-1
    const bool real = (r < NR);
    const int tid = threadIdx.x;        // 256
    float acc = 0.f;
    for (int c4 = tid; c4 < NS_P / 4; c4 += 256) {
        float4 v = make_float4(0.f, 0.f, 0.f, 0.f);
        if (real && c4 < NS / 4)
            v = *reinterpret_cast<const float4*>(A + (size_t)r * NS + c4 * 4);
        acc += (v.x + v.y) + (v.z + v.w);
        __half h0 = __float2half_rn(v.x), h1 = __float2half_rn(v.y);
        __half h2 = __float2half_rn(v.z), h3 = __float2half_rn(v.w);
        const size_t o = (size_t)r * NS_P + c4 * 4;
        *reinterpret_cast<__half2*>(hi + o)     = __halves2half2(h0, h1);
        *reinterpret_cast<__half2*>(hi + o + 2) = __halves2half2(h2, h3);
        *reinterpret_cast<__half2*>(lo + o) = __halves2half2(
            __float2half_rn(v.x - __half2float(h0)),
            __float2half_rn(v.y - __half2float(h1)));
        *reinterpret_cast<__half2*>(lo + o + 2) = __halves2half2(
            __float2half_rn(v.z - __half2float(h2)),
            __float2half_rn(v.w - __half2float(h3)));
    }
    #pragma unroll
    for (int off = 16; off; off >>= 1) acc += __shfl_down_sync(0xffffffffu, acc, off);
    __shared__ float ws[8];
    if ((tid & 31) == 0) ws[tid >> 5] = acc;
    __syncthreads();
    if (tid == 0 && real) {
        float s = 0.f;
        #pragma unroll
        for (int w = 0; w < 8; w++) s += ws[w];
        invdeg[r] = 1.f / (s + 1e-6f);
    }
}

// fp32 [M x >=col0+512] (row stride ld) cols [col0, col0+512) -> fp16 hi/lo
// [MP x 512] zero-padded. Grid = MP blocks x 128 threads.
__global__ void split_cols_k(const float* __restrict__ in, int ld, int col0,
                             __half* __restrict__ hi, __half* __restrict__ lo,
                             int M)
{
    const int r = blockIdx.x;
    const int c = threadIdx.x * 4;
    float4 v = make_float4(0.f, 0.f, 0.f, 0.f);
    if (r < M)
        v = *reinterpret_cast<const float4*>(in + (size_t)r * ld + col0 + c);
    __half h0 = __float2half_rn(v.x), h1 = __float2half_rn(v.y);
    __half h2 = __float2half_rn(v.z), h3 = __float2half_rn(v.w);
    const size_t o = (size_t)r * DD + c;
    *reinterpret_cast<__half2*>(hi + o)     = __halves2half2(h0, h1);
    *reinterpret_cast<__half2*>(hi + o + 2) = __halves2half2(h2, h3);
    *reinterpret_cast<__half2*>(lo + o) = __halves2half2(
        __float2half_rn(v.x - __half2float(h0)),
        __float2half_rn(v.y - __half2float(h1)));
    *reinterpret_cast<__half2*>(lo + o + 2) = __halves2half2(
        __float2half_rn(v.z - __half2float(h2)),
        __float2half_rn(v.w - __half2float(h3)));
}

// Build combined [W|V] fp16 split for all NL layers: out [NL*512 x 1024].
__global__ void splitW_k(const float* __restrict__ W, const float* __restrict__ V,
                         __half* __restrict__ hi, __half* __restrict__ lo)
{
    const int row = blockIdx.x;           // 0 .. NL*512-1
    const int l = row >> 9, k = row & 511;
    const int n = threadIdx.x * 4;        // 256 threads -> 1024 cols
    const float* src = (n < 512) ? (W + ((size_t)l * DD + k) * DD + n)
                                 : (V + ((size_t)l * DD + k) * DD + n - 512);
    float4 v = *reinterpret_cast<const float4*>(src);
    __half h0 = __float2half_rn(v.x), h1 = __float2half_rn(v.y);
    __half h2 = __float2half_rn(v.z), h3 = __float2half_rn(v.w);
    const size_t o = (size_t)row * 1024 + n;
    *reinterpret_cast<__half2*>(hi + o)     = __halves2half2(h0, h1);
    *reinterpret_cast<__half2*>(hi + o + 2) = __halves2half2(h2, h3);
    *reinterpret_cast<__half2*>(lo + o) = __halves2half2(
        __float2half_rn(v.x - __half2float(h0)),
        __float2half_rn(v.y - __half2float(h1)));
    *reinterpret_cast<__half2*>(lo + o + 2) = __halves2half2(
        __float2half_rn(v.z - __half2float(h2)),
        __float2half_rn(v.w - __half2float(h3)));
}

// ---------------------------------------------------------------------------
// Column degrees
// ---------------------------------------------------------------------------
__global__ void colsum_part_k(const float* __restrict__ A, float* __restrict__ part)
{
    int s = blockIdx.x * blockDim.x + threadIdx.x;
    if (s >= NS) return;
    int chunk = blockIdx.y;
    const int rows = NR / COL_CHUNKS;
    const float* p = A + (size_t)(chunk * rows) * NS + s;
    float acc = 0.f;
    for (int r = 0; r < rows; r++) acc += p[(size_t)r * NS];
    part[chunk * NS + s] = acc;
}
__global__ void colsum_fin_k(const float* __restrict__ part, float* __restrict__ invdeg)
{
    int s = blockIdx.x * blockDim.x + threadIdx.x;
    if (s >= NS) return;
    float acc = 0.f;
    #pragma unroll
    for (int c = 0; c < COL_CHUNKS; c++) acc += part[c * NS + s];
    invdeg[s] = 1.f / (acc + 1e-6f);
}

// ---------------------------------------------------------------------------
// Host orchestration
// ---------------------------------------------------------------------------
extern "C" void kernel_launch(void* const* d_in, const int* in_sizes, int n_in,
                              void* d_out, int out_size)
{
    const float* h_s_in = (const float*)d_in[0];  // [NS, DD]
    const float* A      = (const float*)d_in[1];  // [NR, NS]
    const float* r_emb  = (const float*)d_in[2];  // [NR, DD]
    const float* Wr     = (const float*)d_in[3];  // [NL, DD, DD]
    const float* Ws     = (const float*)d_in[4];
    const float* Vr     = (const float*)d_in[5];
    const float* Vs     = (const float*)d_in[6];
    float* out = (float*)d_out;                   // [NR, DD]

    cudaFuncSetAttribute(hmma_gemm_k<0>,
                         cudaFuncAttributeMaxDynamicSharedMemorySize, HM_SMEM);
    cudaFuncSetAttribute(hmma_gemm_k<1>,
                         cudaFuncAttributeMaxDynamicSharedMemorySize, HM_SMEM);

    float *invdr, *invds, *colpart, *fS, *fR, *partR, *partS;
    __half *Ahi, *Alo, *hrhi, *hrlo, *hshi, *hslo, *gshi, *gslo, *grhi, *grlo;
    __half *WShi, *WSlo, *WRhi, *WRlo;
    cudaGetSymbolAddress((void**)&invdr,   g_invdeg_r);
    cudaGetSymbolAddress((void**)&invds,   g_invdeg_s);
    cudaGetSymbolAddress((void**)&colpart, g_colpart);
    cudaGetSymbolAddress((void**)&fS,    g_fS);
    cudaGetSymbolAddress((void**)&fR,    g_fR);
    cudaGetSymbolAddress((void**)&partR, g_partR);
    cudaGetSymbolAddress((void**)&partS, g_partS);
    cudaGetSymbolAddress((void**)&Ahi,  g_Ahi);
    cudaGetSymbolAddress((void**)&Alo,  g_Alo);
    cudaGetSymbolAddress((void**)&hrhi, g_hrhi);
    cudaGetSymbolAddress((void**)&hrlo, g_hrlo);
    cudaGetSymbolAddress((void**)&hshi, g_hshi);
    cudaGetSymbolAddress((void**)&hslo, g_hslo);
    cudaGetSymbolAddress((void**)&gshi, g_gshi);
    cudaGetSymbolAddress((void**)&gslo, g_gslo);
    cudaGetSymbolAddress((void**)&grhi, g_grhi);
    cudaGetSymbolAddress((void**)&grlo, g_grlo);
    cudaGetSymbolAddress((void**)&WShi, g_WShi);
    cudaGetSymbolAddress((void**)&WSlo, g_WSlo);
    cudaGetSymbolAddress((void**)&WRhi, g_WRhi);
    cudaGetSymbolAddress((void**)&WRlo, g_WRlo);

    // 1: h_s split   2: [Ws|Vs] split   3: [Wr|Vr] split   4: fS GEMM (profiled)
    split_cols_k<<<NS_P, 128>>>(h_s_in, DD, 0, hshi, hslo, NS);
    splitW_k<<<NL * DD, 256>>>(Ws, Vs, WShi, WSlo);
    splitW_k<<<NL * DD, 256>>>(Wr, Vr, WRhi, WRlo);

    for (int l = 0; l < NL; l++) {
        const bool last = (l == NL - 1);
        const int NW = last ? 512 : 1024;

        // fS = h_s @ [Ws|Vs][l]   -> fp32 [NS, 1024]
        hmma_gemm_k<0><<<dim3(NW / 128, NS_P / 128, 1), 256, HM_SMEM>>>(
            NS, DD / 32, hshi, hslo, DD,
            WShi + (size_t)l * DD * 1024, WSlo + (size_t)l * DD * 1024, 1024,
            fS, 1024, 0);

        if (l == 0) {
            // one-time conversions, placed after the first GEMM so the
            // profiler window lands on hmma_gemm_k
            split_cols_k<<<NR_P, 128>>>(r_emb, DD, 0, hrhi, hrlo, NR);
            split_rowsA_k<<<NR_P, 256>>>(A, Ahi, Alo, invdr);
            colsum_part_k<<<dim3((NS + 255) / 256, COL_CHUNKS), 256>>>(A, colpart);
            colsum_fin_k<<<(NS + 255) / 256, 256>>>(colpart, invds);
        }

        // fR = h_r @ [Wr|Vr][l]   -> fp32 [NR, 1024]
        hmma_gemm_k<0><<<dim3(NW / 128, NR_P / 128, 1), 256, HM_SMEM>>>(
            NR, DD / 32, hrhi, hrlo, DD,
            WRhi + (size_t)l * DD * 1024, WRlo + (size_t)l * DD * 1024, 1024,
            fR, 1024, 0);

        // gs split (B operand of big GEMM), padded to NS_P rows
        split_cols_k<<<NS_P, 128>>>(fS, 1024, 0, gshi, gslo, NS);

        // h_r' = relu(invdeg_r * (A @ gs) + tr), split-K
        hmma_gemm_k<0><<<dim3(4, NR_P / 128, KSPLIT_R), 256, HM_SMEM>>>(
            NR, NS_P / 32, Ahi, Alo, NS_P, gshi, gslo, DD,
            partR, DD, (size_t)NR * DD);
        if (last) {
            reduce_epi_k<1><<<(NR * 128 + 255) / 256, 256>>>(
                NR, NR, KSPLIT_R, partR, (size_t)NR * DD, invdr, fR, 1024,
                out, nullptr, nullptr);
        } else {
            reduce_epi_k<0><<<(NR_P * 128 + 255) / 256, 256>>>(
                NR, NR_P, KSPLIT_R, partR, (size_t)NR * DD, invdr, fR, 1024,
                nullptr, hrhi, hrlo);

            // gr split (B operand of AT GEMM), padded rows
            split_cols_k<<<NR_P, 128>>>(fR, 1024, 512, grhi, grlo, NR);

            // h_s' = relu(invdeg_s * (A^T @ gr) + ts), A read transposed
            hmma_gemm_k<1><<<dim3(4, NS_P / 128, KSPLIT_S), 256, HM_SMEM>>>(
                NS, KR_P / 32, Ahi, Alo, NS_P, grhi, grlo, DD,
                partS, DD, (size_t)NS * DD);
            reduce_epi_k<0><<<(NS_P * 128 + 255) / 256, 256>>>(
                NS, NS_P, KSPLIT_S, partS, (size_t)NS * DD, invds, fS + 512, 1024,
                nullptr, hshi, hslo);
        }
    }
}

// round 10
// speedup vs baseline: 5.9181x; 1.4125x over previous
#include <cuda_runtime.h>
#include <cuda_fp16.h>
#include <cstdint>

// ---------------------------------------------------------------------------
// Problem constants
// ---------------------------------------------------------------------------
#define NR 20000          // readings
#define NS 5000           // skills
#define DD 512            // embedding dim
#define NL 3              // layers
#define NR_P 20096        // NR padded to 128
#define NS_P 5120         // NS padded to 128
#define KR_P 20032        // NR padded to 32 (K dim of A^T GEMM)
#define COL_CHUNKS 16
#define KSPLIT_R 4        // split-K for A@gs   (grid 4*157*4 = 2512)
#define KSPLIT_S 16       // split-K for A^T@gr (grid 4*40*16 = 2560)

// ---------------------------------------------------------------------------
// Device scratch (no cudaMalloc allowed)
// ---------------------------------------------------------------------------
__device__ float g_invdeg_r[NR];
__device__ float g_invdeg_s[NS];
__device__ float g_colpart[COL_CHUNKS * NS];

__device__ __align__(16) __half g_Ahi[(size_t)NR_P * NS_P];
__device__ __align__(16) __half g_hrhi[(size_t)NR_P * DD];
__device__ __align__(16) __half g_hrlo[(size_t)NR_P * DD];
__device__ __align__(16) __half g_hshi[(size_t)NS_P * DD];
__device__ __align__(16) __half g_hslo[(size_t)NS_P * DD];
__device__ __align__(16) __half g_gshi[(size_t)NS_P * DD];
__device__ __align__(16) __half g_gslo[(size_t)NS_P * DD];
__device__ __align__(16) __half g_grhi[(size_t)NR_P * DD];
__device__ __align__(16) __half g_grlo[(size_t)NR_P * DD];
__device__ __align__(16) __half g_WShi[(size_t)NL * DD * 1024];  // [Ws|Vs]
__device__ __align__(16) __half g_WSlo[(size_t)NL * DD * 1024];
__device__ __align__(16) __half g_WRhi[(size_t)NL * DD * 1024];  // [Wr|Vr]
__device__ __align__(16) __half g_WRlo[(size_t)NL * DD * 1024];

__device__ float g_fS[(size_t)NS * 1024];            // [gs | ts]
__device__ float g_fR[(size_t)NR * 1024];            // [tr | gr]
__device__ float g_partR[(size_t)KSPLIT_R * NR * DD];
__device__ float g_partS[(size_t)KSPLIT_S * NS * DD];

// ---------------------------------------------------------------------------
// PTX helpers (Ampere-era ISA: compiles for plain compute_103 target)
// ---------------------------------------------------------------------------
__device__ __forceinline__ uint32_t smem_u32(const void* p) {
    uint32_t a;
    asm("{ .reg .u64 t; cvta.to.shared.u64 t, %1; cvt.u32.u64 %0, t; }"
        : "=r"(a) : "l"(p));
    return a;
}
__device__ __forceinline__ void cp16(uint32_t dst, const void* src) {
    asm volatile("cp.async.cg.shared.global [%0], [%1], 16;"
                 :: "r"(dst), "l"(src) : "memory");
}
__device__ __forceinline__ void cp_commit() {
    asm volatile("cp.async.commit_group;" ::: "memory");
}
template <int N>
__device__ __forceinline__ void cp_wait() {
    asm volatile("cp.async.wait_group %0;" :: "n"(N) : "memory");
}
__device__ __forceinline__ void ldsm4(uint32_t& r0, uint32_t& r1,
                                      uint32_t& r2, uint32_t& r3, uint32_t a) {
    asm volatile("ldmatrix.sync.aligned.m8n8.x4.shared.b16 {%0,%1,%2,%3}, [%4];"
                 : "=r"(r0), "=r"(r1), "=r"(r2), "=r"(r3) : "r"(a));
}
__device__ __forceinline__ void ldsm4t(uint32_t& r0, uint32_t& r1,
                                       uint32_t& r2, uint32_t& r3, uint32_t a) {
    asm volatile("ldmatrix.sync.aligned.m8n8.x4.trans.shared.b16 {%0,%1,%2,%3}, [%4];"
                 : "=r"(r0), "=r"(r1), "=r"(r2), "=r"(r3) : "r"(a));
}
__device__ __forceinline__ void mma16816(float* d, const uint32_t* a,
                                         const uint32_t* b) {
    asm volatile(
        "mma.sync.aligned.m16n8k16.row.col.f32.f16.f16.f32 "
        "{%0,%1,%2,%3}, {%4,%5,%6,%7}, {%8,%9}, {%0,%1,%2,%3};"
        : "+f"(d[0]), "+f"(d[1]), "+f"(d[2]), "+f"(d[3])
        : "r"(a[0]), "r"(a[1]), "r"(a[2]), "r"(a[3]), "r"(b[0]), "r"(b[1]));
}
// A-normal tile [128m x 32k] (64B rows, 4 segments): conflict-free
__device__ __forceinline__ uint32_t swz(int r, int c16) {
    return (uint32_t)((c16 << 11) + ((r >> 3) << 7) + (((r + 2 * c16) & 7) << 4));
}
// K-major tile [32k x 128cols] (256B rows): XOR swizzle, conflict-free for
// cp.async stores and ldmatrix phases.
__device__ __forceinline__ uint32_t swz_kn(int r, int c) {
    return (uint32_t)(r * 256 + ((c & 8) << 4) + (((c ^ r) & 7) << 4));
}

// ---------------------------------------------------------------------------
// Stage loader. Layout per stage:
//   A_SPLIT=1: Ahi(+0) Alo(+8K) Bhi(+16K) Blo(+24K)  (32 KB)
//   A_SPLIT=0: Ahi(+0)          Bhi(+8K)  Blo(+16K)  (24 KB)
// B source is [K,N] row-major. A: [M,K] (A_TRANS=0) or [K,M] (A_TRANS=1).
// All sources zero-padded -> no guards.
// ---------------------------------------------------------------------------
template <int A_TRANS, int A_SPLIT>
__device__ __forceinline__ void load_stage(uint32_t sb,
    const __half* __restrict__ Ahi, const __half* __restrict__ Alo,
    int lda, int bm,
    const __half* __restrict__ Bhi, const __half* __restrict__ Blo,
    int ldb, int bn, int k0, int tid)
{
    const uint32_t BOFF = A_SPLIT ? 16384u : 8192u;
    #pragma unroll
    for (int i = 0; i < 2; i++) {
        const int idx = tid + i * 256;
        const int r = idx >> 4, c = idx & 15;
        const uint32_t so = swz_kn(r, c);
        const size_t bo = (size_t)(k0 + r) * ldb + bn + c * 8;
        cp16(sb + BOFF + so,        Bhi + bo);
        cp16(sb + BOFF + 8192 + so, Blo + bo);
        if (A_TRANS) {
            const size_t ao = (size_t)(k0 + r) * lda + bm + c * 8;
            cp16(sb + so, Ahi + ao);
            if (A_SPLIT) cp16(sb + 8192 + so, Alo + ao);
        } else {
            const int c16 = idx & 3, ra = idx >> 2;
            const uint32_t soA = swz(ra, c16);
            const size_t ao = (size_t)(bm + ra) * lda + k0 + c16 * 8;
            cp16(sb + soA, Ahi + ao);
            if (A_SPLIT) cp16(sb + 8192 + soA, Alo + ao);
        }
    }
}

// ---------------------------------------------------------------------------
// HMMA GEMM: C[M,N] = op(A)[M,K] @ (Bhi+Blo)[K,N]
//   A_SPLIT=1: A = Ahi+Alo (3-term split product). A_SPLIT=0: A = Ahi only
//   (2-term: Ah*Bh + Ah*Bl). A_TRANS=1 reads A from [K,M] row-major.
//   CTA 128x128, BK=32, multi-stage cp.async, 8 warps as 2M x 4N
//   (warp tile 64x32), 2 CTAs/SM. Split-K over gridDim.z -> plain partials.
// ---------------------------------------------------------------------------
template <int A_TRANS, int A_SPLIT>
__global__ void __launch_bounds__(256, 2)
hmma_gemm_k(int M, int Kc,
            const __half* __restrict__ Ahi, const __half* __restrict__ Alo,
            int lda,
            const __half* __restrict__ Bhi, const __half* __restrict__ Blo,
            int ldb,
            float* __restrict__ C, int ldc, size_t part_stride)
{
    constexpr int STAGE = A_SPLIT ? 32768 : 24576;
    constexpr int NST   = A_SPLIT ? 3 : 4;
    constexpr uint32_t BOFF = A_SPLIT ? 16384u : 8192u;

    extern __shared__ char sm[];
    const uint32_t smb = smem_u32(sm);
    const int tid  = threadIdx.x;
    const int wid  = tid >> 5;
    const int lane = tid & 31;
    const int warp_m = wid & 1;    // 0..1 (64 rows each)
    const int warp_n = wid >> 1;   // 0..3 (32 cols each)
    const int bm = blockIdx.y * 128;
    const int bn = blockIdx.x * 128;

    const int P = gridDim.z, p = blockIdx.z;
    const int kbase = Kc / P, krem = Kc - kbase * P;
    const int kc0 = p * kbase + (p < krem ? p : krem);
    const int kcn = kbase + (p < krem ? 1 : 0);
    C += part_stride * (size_t)p;

    float acc[4][4][4];
    #pragma unroll
    for (int mf = 0; mf < 4; mf++)
        #pragma unroll
        for (int nt = 0; nt < 4; nt++)
            #pragma unroll
            for (int i = 0; i < 4; i++) acc[mf][nt][i] = 0.f;

    // prologue: prefetch NST-1 stages
    #pragma unroll
    for (int s = 0; s < NST - 1; s++) {
        if (s < kcn)
            load_stage<A_TRANS, A_SPLIT>(smb + s * STAGE, Ahi, Alo, lda, bm,
                                         Bhi, Blo, ldb, bn, (kc0 + s) * 32, tid);
        cp_commit();
    }

    // per-lane ldmatrix indices
    const int aN_r  = warp_m * 64 + (lane & 15);        // A normal: m row
    const int aN_ch = lane >> 4;                         // A normal: k chunk
    const int aT_r  = (lane & 7) + ((lane >> 4) << 3);   // A trans: k row off
    const int aT_cb = warp_m * 8 + ((lane >> 3) & 1);    // A trans: m chunk
    const int b_r   = lane & 15;                         // B: k row offset
    const int b_cb  = warp_n * 4 + (lane >> 4);          // B: n chunk base

    for (int ci = 0; ci < kcn; ci++) {
        cp_wait<NST - 2>();
        __syncthreads();
        if (ci + NST - 1 < kcn)
            load_stage<A_TRANS, A_SPLIT>(
                smb + ((ci + NST - 1) % NST) * STAGE, Ahi, Alo, lda, bm,
                Bhi, Blo, ldb, bn, (kc0 + ci + NST - 1) * 32, tid);
        cp_commit();

        const uint32_t sb = smb + (ci % NST) * STAGE;
        #pragma unroll
        for (int ks = 0; ks < 2; ks++) {
            uint32_t ah[4][4], al[4][4], bh[2][4], bl[2][4];
            #pragma unroll
            for (int mf = 0; mf < 4; mf++) {
                if (A_TRANS) {
                    const uint32_t ad =
                        sb + swz_kn(ks * 16 + aT_r, aT_cb + mf * 2);
                    ldsm4t(ah[mf][0], ah[mf][1], ah[mf][2], ah[mf][3], ad);
                    if (A_SPLIT)
                        ldsm4t(al[mf][0], al[mf][1], al[mf][2], al[mf][3],
                               ad + 8192);
                } else {
                    const uint32_t ad =
                        sb + swz(aN_r + mf * 16, ks * 2 + aN_ch);
                    ldsm4(ah[mf][0], ah[mf][1], ah[mf][2], ah[mf][3], ad);
                    if (A_SPLIT)
                        ldsm4(al[mf][0], al[mf][1], al[mf][2], al[mf][3],
                              ad + 8192);
                }
            }
            #pragma unroll
            for (int np = 0; np < 2; np++) {
                const uint32_t bd =
                    sb + BOFF + swz_kn(ks * 16 + b_r, b_cb + np * 2);
                ldsm4t(bh[np][0], bh[np][1], bh[np][2], bh[np][3], bd);
                ldsm4t(bl[np][0], bl[np][1], bl[np][2], bl[np][3], bd + 8192);
            }
            #pragma unroll
            for (int mf = 0; mf < 4; mf++) {
                #pragma unroll
                for (int np = 0; np < 2; np++) {
                    mma16816(acc[mf][np * 2],     ah[mf], &bh[np][0]);
                    mma16816(acc[mf][np * 2 + 1], ah[mf], &bh[np][2]);
                    mma16816(acc[mf][np * 2],     ah[mf], &bl[np][0]);
                    mma16816(acc[mf][np * 2 + 1], ah[mf], &bl[np][2]);
                    if (A_SPLIT) {
                        mma16816(acc[mf][np * 2],     al[mf], &bh[np][0]);
                        mma16816(acc[mf][np * 2 + 1], al[mf], &bh[np][2]);
                    }
                }
            }
        }
    }

    const int row_in = lane >> 2;
    const int col_in = (lane & 3) * 2;
    #pragma unroll
    for (int mf = 0; mf < 4; mf++) {
        #pragma unroll
        for (int h2 = 0; h2 < 2; h2++) {
            const int m = bm + warp_m * 64 + mf * 16 + row_in + h2 * 8;
            if (m >= M) continue;
            #pragma unroll
            for (int nt = 0; nt < 4; nt++) {
                const int n = bn + warp_n * 32 + nt * 8 + col_in;
                float2 o;
                o.x = acc[mf][nt][h2 * 2 + 0];
                o.y = acc[mf][nt][h2 * 2 + 1];
                *reinterpret_cast<float2*>(C + (size_t)m * ldc + n) = o;
            }
        }
    }
}

#define SMEM_SPLIT (3 * 32768)
#define SMEM_NOSPL (4 * 24576)

// ---------------------------------------------------------------------------
// reduce + epilogue: v = relu(invdeg[m] * sum_p part[p] + add[m,n])
//   WRITE_F32=1: fp32 out (rows < M). Else fp16 hi/lo split, padded rows zero.
// ---------------------------------------------------------------------------
template <int WRITE_F32>
__global__ void reduce_epi_k(int M, int MP, int P,
                             const float* __restrict__ part, size_t pstride,
                             const float* __restrict__ invdeg,
                             const float* __restrict__ add, int ld_add,
                             float* __restrict__ out32,
                             __half* __restrict__ hi, __half* __restrict__ lo)
{
    int idx = blockIdx.x * 256 + threadIdx.x;   // over MP * 128 float4s
    if (idx >= MP * 128) return;
    int m = idx >> 7, q = (idx & 127) << 2;
    float4 o = make_float4(0.f, 0.f, 0.f, 0.f);
    if (m < M) {
        float4 s = make_float4(0.f, 0.f, 0.f, 0.f);
        for (int pp = 0; pp < P; pp++) {
            const float4 v = *reinterpret_cast<const float4*>(
                part + pp * pstride + (size_t)m * DD + q);
            s.x += v.x; s.y += v.y; s.z += v.z; s.w += v.w;
        }
        const float sc = invdeg[m];
        const float4 a = *reinterpret_cast<const float4*>(
            add + (size_t)m * ld_add + q);
        o.x = fmaxf(fmaf(sc, s.x, a.x), 0.f);
        o.y = fmaxf(fmaf(sc, s.y, a.y), 0.f);
        o.z = fmaxf(fmaf(sc, s.z, a.z), 0.f);
        o.w = fmaxf(fmaf(sc, s.w, a.w), 0.f);
    }
    if (WRITE_F32) {
        if (m < M)
            *reinterpret_cast<float4*>(out32 + (size_t)m * DD + q) = o;
    } else {
        __half h0 = __float2half_rn(o.x), h1 = __float2half_rn(o.y);
        __half h2 = __float2half_rn(o.z), h3 = __float2half_rn(o.w);
        const size_t off = (size_t)m * DD + q;
        *reinterpret_cast<__half2*>(hi + off)     = __halves2half2(h0, h1);
        *reinterpret_cast<__half2*>(hi + off + 2) = __halves2half2(h2, h3);
        *reinterpret_cast<__half2*>(lo + off) = __halves2half2(
            __float2half_rn(o.x - __half2float(h0)),
            __float2half_rn(o.y - __half2float(h1)));
        *reinterpret_cast<__half2*>(lo + off + 2) = __halves2half2(
            __float2half_rn(o.z - __half2float(h2)),
            __float2half_rn(o.w - __half2float(h3)));
    }
}

// ---------------------------------------------------------------------------
// Conversions
// ---------------------------------------------------------------------------
// A [NR x 5000] fp32 -> hi [NR_P x NS_P] fp16 (no lo), fused with row degrees.
__global__ void splitA_hi_k(const float* __restrict__ A,
                            __half* __restrict__ hi,
                            float* __restrict__ invdeg)
{
    const int r = blockIdx.x;           // 0..NR_P-1
    const bool real = (r < NR);
    const int tid = threadIdx.x;        // 256
    float acc = 0.f;
    for (int c4 = tid; c4 < NS_P / 4; c4 += 256) {
        float4 v = make_float4(0.f, 0.f, 0.f, 0.f);
        if (real && c4 < NS / 4)
            v = *reinterpret_cast<const float4*>(A + (size_t)r * NS + c4 * 4);
        acc += (v.x + v.y) + (v.z + v.w);
        const size_t o = (size_t)r * NS_P + c4 * 4;
        *reinterpret_cast<__half2*>(hi + o) =
            __halves2half2(__float2half_rn(v.x), __float2half_rn(v.y));
        *reinterpret_cast<__half2*>(hi + o + 2) =
            __halves2half2(__float2half_rn(v.z), __float2half_rn(v.w));
    }
    #pragma unroll
    for (int off = 16; off; off >>= 1) acc += __shfl_down_sync(0xffffffffu, acc, off);
    __shared__ float ws[8];
    if ((tid & 31) == 0) ws[tid >> 5] = acc;
    __syncthreads();
    if (tid == 0 && real) {
        float s = 0.f;
        #pragma unroll
        for (int w = 0; w < 8; w++) s += ws[w];
        invdeg[r] = 1.f / (s + 1e-6f);
    }
}

// fp32 [M x >=col0+512] (row stride ld) cols [col0, col0+512) -> fp16 hi/lo
// [MP x 512] zero-padded. Grid = MP blocks x 128 threads.
__global__ void split_cols_k(const float* __restrict__ in, int ld, int col0,
                             __half* __restrict__ hi, __half* __restrict__ lo,
                             int M)
{
    const int r = blockIdx.x;
    const int c = threadIdx.x * 4;
    float4 v = make_float4(0.f, 0.f, 0.f, 0.f);
    if (r < M)
        v = *reinterpret_cast<const float4*>(in + (size_t)r * ld + col0 + c);
    __half h0 = __float2half_rn(v.x), h1 = __float2half_rn(v.y);
    __half h2 = __float2half_rn(v.z), h3 = __float2half_rn(v.w);
    const size_t o = (size_t)r * DD + c;
    *reinterpret_cast<__half2*>(hi + o)     = __halves2half2(h0, h1);
    *reinterpret_cast<__half2*>(hi + o + 2) = __halves2half2(h2, h3);
    *reinterpret_cast<__half2*>(lo + o) = __halves2half2(
        __float2half_rn(v.x - __half2float(h0)),
        __float2half_rn(v.y - __half2float(h1)));
    *reinterpret_cast<__half2*>(lo + o + 2) = __halves2half2(
        __float2half_rn(v.z - __half2float(h2)),
        __float2half_rn(v.w - __half2float(h3)));
}

// Build combined [W|V] fp16 split for all NL layers: out [NL*512 x 1024].
__global__ void splitW_k(const float* __restrict__ W, const float* __restrict__ V,
                         __half* __restrict__ hi, __half* __restrict__ lo)
{
    const int row = blockIdx.x;           // 0 .. NL*512-1
    const int l = row >> 9, k = row & 511;
    const int n = threadIdx.x * 4;        // 256 threads -> 1024 cols
    const float* src = (n < 512) ? (W + ((size_t)l * DD + k) * DD + n)
                                 : (V + ((size_t)l * DD + k) * DD + n - 512);
    float4 v = *reinterpret_cast<const float4*>(src);
    __half h0 = __float2half_rn(v.x), h1 = __float2half_rn(v.y);
    __half h2 = __float2half_rn(v.z), h3 = __float2half_rn(v.w);
    const size_t o = (size_t)row * 1024 + n;
    *reinterpret_cast<__half2*>(hi + o)     = __halves2half2(h0, h1);
    *reinterpret_cast<__half2*>(hi + o + 2) = __halves2half2(h2, h3);
    *reinterpret_cast<__half2*>(lo + o) = __halves2half2(
        __float2half_rn(v.x - __half2float(h0)),
        __float2half_rn(v.y - __half2float(h1)));
    *reinterpret_cast<__half2*>(lo + o + 2) = __halves2half2(
        __float2half_rn(v.z - __half2float(h2)),
        __float2half_rn(v.w - __half2float(h3)));
}

// ---------------------------------------------------------------------------
// Column degrees
// ---------------------------------------------------------------------------
__global__ void colsum_part_k(const float* __restrict__ A, float* __restrict__ part)
{
    int s = blockIdx.x * blockDim.x + threadIdx.x;
    if (s >= NS) return;
    int chunk = blockIdx.y;
    const int rows = NR / COL_CHUNKS;
    const float* p = A + (size_t)(chunk * rows) * NS + s;
    float acc = 0.f;
    for (int r = 0; r < rows; r++) acc += p[(size_t)r * NS];
    part[chunk * NS + s] = acc;
}
__global__ void colsum_fin_k(const float* __restrict__ part, float* __restrict__ invdeg)
{
    int s = blockIdx.x * blockDim.x + threadIdx.x;
    if (s >= NS) return;
    float acc = 0.f;
    #pragma unroll
    for (int c = 0; c < COL_CHUNKS; c++) acc += part[c * NS + s];
    invdeg[s] = 1.f / (acc + 1e-6f);
}

// ---------------------------------------------------------------------------
// Host orchestration
// ---------------------------------------------------------------------------
extern "C" void kernel_launch(void* const* d_in, const int* in_sizes, int n_in,
                              void* d_out, int out_size)
{
    const float* h_s_in = (const float*)d_in[0];  // [NS, DD]
    const float* A      = (const float*)d_in[1];  // [NR, NS]
    const float* r_emb  = (const float*)d_in[2];  // [NR, DD]
    const float* Wr     = (const float*)d_in[3];  // [NL, DD, DD]
    const float* Ws     = (const float*)d_in[4];
    const float* Vr     = (const float*)d_in[5];
    const float* Vs     = (const float*)d_in[6];
    float* out = (float*)d_out;                   // [NR, DD]

    cudaFuncSetAttribute(hmma_gemm_k<0, 1>,
                         cudaFuncAttributeMaxDynamicSharedMemorySize, SMEM_SPLIT);
    cudaFuncSetAttribute(hmma_gemm_k<0, 0>,
                         cudaFuncAttributeMaxDynamicSharedMemorySize, SMEM_NOSPL);
    cudaFuncSetAttribute(hmma_gemm_k<1, 0>,
                         cudaFuncAttributeMaxDynamicSharedMemorySize, SMEM_NOSPL);

    float *invdr, *invds, *colpart, *fS, *fR, *partR, *partS;
    __half *Ahi, *hrhi, *hrlo, *hshi, *hslo, *gshi, *gslo, *grhi, *grlo;
    __half *WShi, *WSlo, *WRhi, *WRlo;
    cudaGetSymbolAddress((void**)&invdr,   g_invdeg_r);
    cudaGetSymbolAddress((void**)&invds,   g_invdeg_s);
    cudaGetSymbolAddress((void**)&colpart, g_colpart);
    cudaGetSymbolAddress((void**)&fS,    g_fS);
    cudaGetSymbolAddress((void**)&fR,    g_fR);
    cudaGetSymbolAddress((void**)&partR, g_partR);
    cudaGetSymbolAddress((void**)&partS, g_partS);
    cudaGetSymbolAddress((void**)&Ahi,  g_Ahi);
    cudaGetSymbolAddress((void**)&hrhi, g_hrhi);
    cudaGetSymbolAddress((void**)&hrlo, g_hrlo);
    cudaGetSymbolAddress((void**)&hshi, g_hshi);
    cudaGetSymbolAddress((void**)&hslo, g_hslo);
    cudaGetSymbolAddress((void**)&gshi, g_gshi);
    cudaGetSymbolAddress((void**)&gslo, g_gslo);
    cudaGetSymbolAddress((void**)&grhi, g_grhi);
    cudaGetSymbolAddress((void**)&grlo, g_grlo);
    cudaGetSymbolAddress((void**)&WShi, g_WShi);
    cudaGetSymbolAddress((void**)&WSlo, g_WSlo);
    cudaGetSymbolAddress((void**)&WRhi, g_WRhi);
    cudaGetSymbolAddress((void**)&WRlo, g_WRlo);

    split_cols_k<<<NS_P, 128>>>(h_s_in, DD, 0, hshi, hslo, NS);
    splitW_k<<<NL * DD, 256>>>(Ws, Vs, WShi, WSlo);
    splitW_k<<<NL * DD, 256>>>(Wr, Vr, WRhi, WRlo);

    for (int l = 0; l < NL; l++) {
        const bool last = (l == NL - 1);
        const int NW = last ? 512 : 1024;

        // fS = h_s @ [Ws|Vs][l]   -> fp32 [NS, 1024]
        hmma_gemm_k<0, 1><<<dim3(NW / 128, NS_P / 128, 1), 256, SMEM_SPLIT>>>(
            NS, DD / 32, hshi, hslo, DD,
            WShi + (size_t)l * DD * 1024, WSlo + (size_t)l * DD * 1024, 1024,
            fS, 1024, 0);

        if (l == 0) {
            split_cols_k<<<NR_P, 128>>>(r_emb, DD, 0, hrhi, hrlo, NR);
            splitA_hi_k<<<NR_P, 256>>>(A, Ahi, invdr);
            colsum_part_k<<<dim3((NS + 255) / 256, COL_CHUNKS), 256>>>(A, colpart);
            colsum_fin_k<<<(NS + 255) / 256, 256>>>(colpart, invds);
        }

        // fR = h_r @ [Wr|Vr][l]   -> fp32 [NR, 1024]
        hmma_gemm_k<0, 1><<<dim3(NW / 128, NR_P / 128, 1), 256, SMEM_SPLIT>>>(
            NR, DD / 32, hrhi, hrlo, DD,
            WRhi + (size_t)l * DD * 1024, WRlo + (size_t)l * DD * 1024, 1024,
            fR, 1024, 0);

        // gs split (B operand of big GEMM), padded to NS_P rows
        split_cols_k<<<NS_P, 128>>>(fS, 1024, 0, gshi, gslo, NS);

        // h_r' = relu(invdeg_r * (A @ gs) + tr), A single fp16, split-K
        hmma_gemm_k<0, 0><<<dim3(4, NR_P / 128, KSPLIT_R), 256, SMEM_NOSPL>>>(
            NR, NS_P / 32, Ahi, nullptr, NS_P, gshi, gslo, DD,
            partR, DD, (size_t)NR * DD);
        if (last) {
            reduce_epi_k<1><<<(NR * 128 + 255) / 256, 256>>>(
                NR, NR, KSPLIT_R, partR, (size_t)NR * DD, invdr, fR, 1024,
                out, nullptr, nullptr);
        } else {
            reduce_epi_k<0><<<(NR_P * 128 + 255) / 256, 256>>>(
                NR, NR_P, KSPLIT_R, partR, (size_t)NR * DD, invdr, fR, 1024,
                nullptr, hrhi, hrlo);

            // gr split (B operand of AT GEMM), padded rows
            split_cols_k<<<NR_P, 128>>>(fR, 1024, 512, grhi, grlo, NR);

            // h_s' = relu(invdeg_s * (A^T @ gr) + ts), A read transposed
            hmma_gemm_k<1, 0><<<dim3(4, NS_P / 128, KSPLIT_S), 256, SMEM_NOSPL>>>(
                NS, KR_P / 32, Ahi, nullptr, NS_P, grhi, grlo, DD,
                partS, DD, (size_t)NS * DD);
            reduce_epi_k<0><<<(NS_P * 128 + 255) / 256, 256>>>(
                NS, NS_P, KSPLIT_S, partS, (size_t)NS * DD, invds, fS + 512, 1024,
                nullptr, hshi, hslo);
        }
    }
}

// round 11
// speedup vs baseline: 7.7522x; 1.3099x over previous
#include <cuda_runtime.h>
#include <cuda_fp16.h>
#include <cstdint>

// ---------------------------------------------------------------------------
// Problem constants
// ---------------------------------------------------------------------------
#define NR 20000          // readings
#define NS 5000           // skills
#define DD 512            // embedding dim
#define NL 3              // layers
#define NR_P 20096        // NR padded to 128
#define NS_P 5120         // NS padded to 128
#define KR_P 20032        // NR padded to 32 (K dim of A^T GEMM)
#define COL_CHUNKS 16
#define KSPLIT_R 4        // split-K for A@gs   (grid 4*157*4 = 2512)
#define KSPLIT_S 16       // split-K for A^T@gr (grid 4*40*16 = 2560)

// ---------------------------------------------------------------------------
// Device scratch (no cudaMalloc allowed)
// ---------------------------------------------------------------------------
__device__ float g_invdeg_r[NR];
__device__ float g_invdeg_s[NS];
__device__ float g_colpart[COL_CHUNKS * NS];

__device__ __align__(16) __half g_Ahi[(size_t)NR_P * NS_P];
__device__ __align__(16) __half g_hrhi[(size_t)NR_P * DD];
__device__ __align__(16) __half g_hrlo[(size_t)NR_P * DD];
__device__ __align__(16) __half g_hshi[(size_t)NS_P * DD];
__device__ __align__(16) __half g_hslo[(size_t)NS_P * DD];
__device__ __align__(16) __half g_gshi[(size_t)NS_P * DD];
__device__ __align__(16) __half g_grhi[(size_t)NR_P * DD];
__device__ __align__(16) __half g_WShi[(size_t)NL * DD * 1024];  // [Ws|Vs]
__device__ __align__(16) __half g_WSlo[(size_t)NL * DD * 1024];
__device__ __align__(16) __half g_WRhi[(size_t)NL * DD * 1024];  // [Wr|Vr]
__device__ __align__(16) __half g_WRlo[(size_t)NL * DD * 1024];

__device__ float g_fS[(size_t)NS * 1024];            // [gs | ts]
__device__ float g_fR[(size_t)NR * 1024];            // [tr | gr]
__device__ float g_partR[(size_t)KSPLIT_R * NR * DD];
__device__ float g_partS[(size_t)KSPLIT_S * NS * DD];

// ---------------------------------------------------------------------------
// PTX helpers (Ampere-era ISA: compiles for plain compute_103 target)
// ---------------------------------------------------------------------------
__device__ __forceinline__ uint32_t smem_u32(const void* p) {
    uint32_t a;
    asm("{ .reg .u64 t; cvta.to.shared.u64 t, %1; cvt.u32.u64 %0, t; }"
        : "=r"(a) : "l"(p));
    return a;
}
__device__ __forceinline__ void cp16(uint32_t dst, const void* src) {
    asm volatile("cp.async.cg.shared.global [%0], [%1], 16;"
                 :: "r"(dst), "l"(src) : "memory");
}
__device__ __forceinline__ void cp_commit() {
    asm volatile("cp.async.commit_group;" ::: "memory");
}
template <int N>
__device__ __forceinline__ void cp_wait() {
    asm volatile("cp.async.wait_group %0;" :: "n"(N) : "memory");
}
__device__ __forceinline__ void ldsm4(uint32_t& r0, uint32_t& r1,
                                      uint32_t& r2, uint32_t& r3, uint32_t a) {
    asm volatile("ldmatrix.sync.aligned.m8n8.x4.shared.b16 {%0,%1,%2,%3}, [%4];"
                 : "=r"(r0), "=r"(r1), "=r"(r2), "=r"(r3) : "r"(a));
}
__device__ __forceinline__ void ldsm4t(uint32_t& r0, uint32_t& r1,
                                       uint32_t& r2, uint32_t& r3, uint32_t a) {
    asm volatile("ldmatrix.sync.aligned.m8n8.x4.trans.shared.b16 {%0,%1,%2,%3}, [%4];"
                 : "=r"(r0), "=r"(r1), "=r"(r2), "=r"(r3) : "r"(a));
}
__device__ __forceinline__ void mma16816(float* d, const uint32_t* a,
                                         const uint32_t* b) {
    asm volatile(
        "mma.sync.aligned.m16n8k16.row.col.f32.f16.f16.f32 "
        "{%0,%1,%2,%3}, {%4,%5,%6,%7}, {%8,%9}, {%0,%1,%2,%3};"
        : "+f"(d[0]), "+f"(d[1]), "+f"(d[2]), "+f"(d[3])
        : "r"(a[0]), "r"(a[1]), "r"(a[2]), "r"(a[3]), "r"(b[0]), "r"(b[1]));
}
// A-normal tile [128m x 32k] (64B rows, 4 segments): conflict-free
__device__ __forceinline__ uint32_t swz(int r, int c16) {
    return (uint32_t)((c16 << 11) + ((r >> 3) << 7) + (((r + 2 * c16) & 7) << 4));
}
// K-major tile [32k x 128cols] (256B rows): XOR swizzle, conflict-free for
// cp.async stores and ldmatrix phases.
__device__ __forceinline__ uint32_t swz_kn(int r, int c) {
    return (uint32_t)(r * 256 + ((c & 8) << 4) + (((c ^ r) & 7) << 4));
}

// ---------------------------------------------------------------------------
// Stage layout (8 KB units):
//   Ahi(+0) [Alo(+8K) if A_SPLIT] Bhi(+AOFF) [Blo(+AOFF+8K) if B_SPLIT]
// ---------------------------------------------------------------------------
template <int A_TRANS, int A_SPLIT, int B_SPLIT>
__device__ __forceinline__ void load_stage(uint32_t sb,
    const __half* __restrict__ Ahi, const __half* __restrict__ Alo,
    int lda, int bm,
    const __half* __restrict__ Bhi, const __half* __restrict__ Blo,
    int ldb, int bn, int k0, int tid)
{
    const uint32_t BOFF = A_SPLIT ? 16384u : 8192u;
    #pragma unroll
    for (int i = 0; i < 2; i++) {
        const int idx = tid + i * 256;
        const int r = idx >> 4, c = idx & 15;
        const uint32_t so = swz_kn(r, c);
        const size_t bo = (size_t)(k0 + r) * ldb + bn + c * 8;
        cp16(sb + BOFF + so, Bhi + bo);
        if (B_SPLIT) cp16(sb + BOFF + 8192 + so, Blo + bo);
        if (A_TRANS) {
            const size_t ao = (size_t)(k0 + r) * lda + bm + c * 8;
            cp16(sb + so, Ahi + ao);
            if (A_SPLIT) cp16(sb + 8192 + so, Alo + ao);
        } else {
            const int c16 = idx & 3, ra = idx >> 2;
            const uint32_t soA = swz(ra, c16);
            const size_t ao = (size_t)(bm + ra) * lda + k0 + c16 * 8;
            cp16(sb + soA, Ahi + ao);
            if (A_SPLIT) cp16(sb + 8192 + soA, Alo + ao);
        }
    }
}

// ---------------------------------------------------------------------------
// HMMA GEMM: C[M,N] = op(A)[M,K] @ B[K,N]
//   A = Ahi (+Alo if A_SPLIT); B = Bhi (+Blo if B_SPLIT); split-product terms
//   kept: Ah*Bh (+Ah*Bl if B_SPLIT) (+Al*Bh if A_SPLIT). A_TRANS=1 reads A
//   from [K,M] row-major. CTA 128x128, BK=32, deep cp.async pipeline,
//   8 warps as 2M x 4N (warp tile 64x32), 2 CTAs/SM. Split-K over gridDim.z.
// ---------------------------------------------------------------------------
template <int A_TRANS, int A_SPLIT, int B_SPLIT>
__global__ void __launch_bounds__(256, 2)
hmma_gemm_k(int M, int Kc,
            const __half* __restrict__ Ahi, const __half* __restrict__ Alo,
            int lda,
            const __half* __restrict__ Bhi, const __half* __restrict__ Blo,
            int ldb,
            float* __restrict__ C, int ldc, size_t part_stride)
{
    constexpr int STAGE = 8192 * (2 + A_SPLIT + B_SPLIT);
    constexpr int NST   = (A_SPLIT || B_SPLIT) ? 3 : 6;
    constexpr uint32_t BOFF = A_SPLIT ? 16384u : 8192u;

    extern __shared__ char sm[];
    const uint32_t smb = smem_u32(sm);
    const int tid  = threadIdx.x;
    const int wid  = tid >> 5;
    const int lane = tid & 31;
    const int warp_m = wid & 1;    // 0..1 (64 rows each)
    const int warp_n = wid >> 1;   // 0..3 (32 cols each)
    const int bm = blockIdx.y * 128;
    const int bn = blockIdx.x * 128;

    const int P = gridDim.z, p = blockIdx.z;
    const int kbase = Kc / P, krem = Kc - kbase * P;
    const int kc0 = p * kbase + (p < krem ? p : krem);
    const int kcn = kbase + (p < krem ? 1 : 0);
    C += part_stride * (size_t)p;

    float acc[4][4][4];
    #pragma unroll
    for (int mf = 0; mf < 4; mf++)
        #pragma unroll
        for (int nt = 0; nt < 4; nt++)
            #pragma unroll
            for (int i = 0; i < 4; i++) acc[mf][nt][i] = 0.f;

    // prologue: prefetch NST-1 stages
    #pragma unroll
    for (int s = 0; s < NST - 1; s++) {
        if (s < kcn)
            load_stage<A_TRANS, A_SPLIT, B_SPLIT>(
                smb + s * STAGE, Ahi, Alo, lda, bm,
                Bhi, Blo, ldb, bn, (kc0 + s) * 32, tid);
        cp_commit();
    }

    // per-lane ldmatrix indices
    const int aN_r  = warp_m * 64 + (lane & 15);        // A normal: m row
    const int aN_ch = lane >> 4;                         // A normal: k chunk
    const int aT_r  = (lane & 7) + ((lane >> 4) << 3);   // A trans: k row off
    const int aT_cb = warp_m * 8 + ((lane >> 3) & 1);    // A trans: m chunk
    const int b_r   = lane & 15;                         // B: k row offset
    const int b_cb  = warp_n * 4 + (lane >> 4);          // B: n chunk base

    for (int ci = 0; ci < kcn; ci++) {
        cp_wait<NST - 2>();
        __syncthreads();
        if (ci + NST - 1 < kcn)
            load_stage<A_TRANS, A_SPLIT, B_SPLIT>(
                smb + ((ci + NST - 1) % NST) * STAGE, Ahi, Alo, lda, bm,
                Bhi, Blo, ldb, bn, (kc0 + ci + NST - 1) * 32, tid);
        cp_commit();

        const uint32_t sb = smb + (ci % NST) * STAGE;
        #pragma unroll
        for (int ks = 0; ks < 2; ks++) {
            uint32_t ah[4][4], al[4][4], bh[2][4], bl[2][4];
            #pragma unroll
            for (int mf = 0; mf < 4; mf++) {
                if (A_TRANS) {
                    const uint32_t ad =
                        sb + swz_kn(ks * 16 + aT_r, aT_cb + mf * 2);
                    ldsm4t(ah[mf][0], ah[mf][1], ah[mf][2], ah[mf][3], ad);
                    if (A_SPLIT)
                        ldsm4t(al[mf][0], al[mf][1], al[mf][2], al[mf][3],
                               ad + 8192);
                } else {
                    const uint32_t ad =
                        sb + swz(aN_r + mf * 16, ks * 2 + aN_ch);
                    ldsm4(ah[mf][0], ah[mf][1], ah[mf][2], ah[mf][3], ad);
                    if (A_SPLIT)
                        ldsm4(al[mf][0], al[mf][1], al[mf][2], al[mf][3],
                              ad + 8192);
                }
            }
            #pragma unroll
            for (int np = 0; np < 2; np++) {
                const uint32_t bd =
                    sb + BOFF + swz_kn(ks * 16 + b_r, b_cb + np * 2);
                ldsm4t(bh[np][0], bh[np][1], bh[np][2], bh[np][3], bd);
                if (B_SPLIT)
                    ldsm4t(bl[np][0], bl[np][1], bl[np][2], bl[np][3],
                           bd + 8192);
            }
            #pragma unroll
            for (int mf = 0; mf < 4; mf++) {
                #pragma unroll
                for (int np = 0; np < 2; np++) {
                    mma16816(acc[mf][np * 2],     ah[mf], &bh[np][0]);
                    mma16816(acc[mf][np * 2 + 1], ah[mf], &bh[np][2]);
                    if (B_SPLIT) {
                        mma16816(acc[mf][np * 2],     ah[mf], &bl[np][0]);
                        mma16816(acc[mf][np * 2 + 1], ah[mf], &bl[np][2]);
                    }
                    if (A_SPLIT) {
                        mma16816(acc[mf][np * 2],     al[mf], &bh[np][0]);
                        mma16816(acc[mf][np * 2 + 1], al[mf], &bh[np][2]);
                    }
                }
            }
        }
    }

    const int row_in = lane >> 2;
    const int col_in = (lane & 3) * 2;
    #pragma unroll
    for (int mf = 0; mf < 4; mf++) {
        #pragma unroll
        for (int h2 = 0; h2 < 2; h2++) {
            const int m = bm + warp_m * 64 + mf * 16 + row_in + h2 * 8;
            if (m >= M) continue;
            #pragma unroll
            for (int nt = 0; nt < 4; nt++) {
                const int n = bn + warp_n * 32 + nt * 8 + col_in;
                float2 o;
                o.x = acc[mf][nt][h2 * 2 + 0];
                o.y = acc[mf][nt][h2 * 2 + 1];
                *reinterpret_cast<float2*>(C + (size_t)m * ldc + n) = o;
            }
        }
    }
}

#define SMEM_SPLIT (3 * 32768)   // small GEMMs: 3 stages x 32KB
#define SMEM_1TERM (6 * 16384)   // big GEMMs:   6 stages x 16KB

// ---------------------------------------------------------------------------
// reduce + epilogue: v = relu(invdeg[m] * sum_p part[p] + add[m,n])
//   WRITE_F32=1: fp32 out (rows < M). Else fp16 hi/lo split, padded rows zero.
// ---------------------------------------------------------------------------
template <int WRITE_F32>
__global__ void reduce_epi_k(int M, int MP, int P,
                             const float* __restrict__ part, size_t pstride,
                             const float* __restrict__ invdeg,
                             const float* __restrict__ add, int ld_add,
                             float* __restrict__ out32,
                             __half* __restrict__ hi, __half* __restrict__ lo)
{
    int idx = blockIdx.x * 256 + threadIdx.x;   // over MP * 128 float4s
    if (idx >= MP * 128) return;
    int m = idx >> 7, q = (idx & 127) << 2;
    float4 o = make_float4(0.f, 0.f, 0.f, 0.f);
    if (m < M) {
        float4 s = make_float4(0.f, 0.f, 0.f, 0.f);
        for (int pp = 0; pp < P; pp++) {
            const float4 v = *reinterpret_cast<const float4*>(
                part + pp * pstride + (size_t)m * DD + q);
            s.x += v.x; s.y += v.y; s.z += v.z; s.w += v.w;
        }
        const float sc = invdeg[m];
        const float4 a = *reinterpret_cast<const float4*>(
            add + (size_t)m * ld_add + q);
        o.x = fmaxf(fmaf(sc, s.x, a.x), 0.f);
        o.y = fmaxf(fmaf(sc, s.y, a.y), 0.f);
        o.z = fmaxf(fmaf(sc, s.z, a.z), 0.f);
        o.w = fmaxf(fmaf(sc, s.w, a.w), 0.f);
    }
    if (WRITE_F32) {
        if (m < M)
            *reinterpret_cast<float4*>(out32 + (size_t)m * DD + q) = o;
    } else {
        __half h0 = __float2half_rn(o.x), h1 = __float2half_rn(o.y);
        __half h2 = __float2half_rn(o.z), h3 = __float2half_rn(o.w);
        const size_t off = (size_t)m * DD + q;
        *reinterpret_cast<__half2*>(hi + off)     = __halves2half2(h0, h1);
        *reinterpret_cast<__half2*>(hi + off + 2) = __halves2half2(h2, h3);
        *reinterpret_cast<__half2*>(lo + off) = __halves2half2(
            __float2half_rn(o.x - __half2float(h0)),
            __float2half_rn(o.y - __half2float(h1)));
        *reinterpret_cast<__half2*>(lo + off + 2) = __halves2half2(
            __float2half_rn(o.z - __half2float(h2)),
            __float2half_rn(o.w - __half2float(h3)));
    }
}

// ---------------------------------------------------------------------------
// Conversions
// ---------------------------------------------------------------------------
// A [NR x 5000] fp32 -> hi [NR_P x NS_P] fp16, fused with row degrees.
__global__ void splitA_hi_k(const float* __restrict__ A,
                            __half* __restrict__ hi,
                            float* __restrict__ invdeg)
{
    const int r = blockIdx.x;           // 0..NR_P-1
    const bool real = (r < NR);
    const int tid = threadIdx.x;        // 256
    float acc = 0.f;
    for (int c4 = tid; c4 < NS_P / 4; c4 += 256) {
        float4 v = make_float4(0.f, 0.f, 0.f, 0.f);
        if (real && c4 < NS / 4)
            v = *reinterpret_cast<const float4*>(A + (size_t)r * NS + c4 * 4);
        acc += (v.x + v.y) + (v.z + v.w);
        const size_t o = (size_t)r * NS_P + c4 * 4;
        *reinterpret_cast<__half2*>(hi + o) =
            __halves2half2(__float2half_rn(v.x), __float2half_rn(v.y));
        *reinterpret_cast<__half2*>(hi + o + 2) =
            __halves2half2(__float2half_rn(v.z), __float2half_rn(v.w));
    }
    #pragma unroll
    for (int off = 16; off; off >>= 1) acc += __shfl_down_sync(0xffffffffu, acc, off);
    __shared__ float ws[8];
    if ((tid & 31) == 0) ws[tid >> 5] = acc;
    __syncthreads();
    if (tid == 0 && real) {
        float s = 0.f;
        #pragma unroll
        for (int w = 0; w < 8; w++) s += ws[w];
        invdeg[r] = 1.f / (s + 1e-6f);
    }
}

// fp32 cols [col0,col0+512) of [M x ld] -> fp16 hi/lo [MP x 512] zero-padded.
__global__ void split_cols_k(const float* __restrict__ in, int ld, int col0,
                             __half* __restrict__ hi, __half* __restrict__ lo,
                             int M)
{
    const int r = blockIdx.x;
    const int c = threadIdx.x * 4;
    float4 v = make_float4(0.f, 0.f, 0.f, 0.f);
    if (r < M)
        v = *reinterpret_cast<const float4*>(in + (size_t)r * ld + col0 + c);
    __half h0 = __float2half_rn(v.x), h1 = __float2half_rn(v.y);
    __half h2 = __float2half_rn(v.z), h3 = __float2half_rn(v.w);
    const size_t o = (size_t)r * DD + c;
    *reinterpret_cast<__half2*>(hi + o)     = __halves2half2(h0, h1);
    *reinterpret_cast<__half2*>(hi + o + 2) = __halves2half2(h2, h3);
    *reinterpret_cast<__half2*>(lo + o) = __halves2half2(
        __float2half_rn(v.x - __half2float(h0)),
        __float2half_rn(v.y - __half2float(h1)));
    *reinterpret_cast<__half2*>(lo + o + 2) = __halves2half2(
        __float2half_rn(v.z - __half2float(h2)),
        __float2half_rn(v.w - __half2float(h3)));
}

// fp32 cols [col0,col0+512) -> fp16 hi ONLY, [MP x 512] zero-padded.
__global__ void split_cols_hi_k(const float* __restrict__ in, int ld, int col0,
                                __half* __restrict__ hi, int M)
{
    const int r = blockIdx.x;
    const int c = threadIdx.x * 4;
    float4 v = make_float4(0.f, 0.f, 0.f, 0.f);
    if (r < M)
        v = *reinterpret_cast<const float4*>(in + (size_t)r * ld + col0 + c);
    const size_t o = (size_t)r * DD + c;
    *reinterpret_cast<__half2*>(hi + o) =
        __halves2half2(__float2half_rn(v.x), __float2half_rn(v.y));
    *reinterpret_cast<__half2*>(hi + o + 2) =
        __halves2half2(__float2half_rn(v.z), __float2half_rn(v.w));
}

// Build combined [W|V] fp16 split for all NL layers: out [NL*512 x 1024].
__global__ void splitW_k(const float* __restrict__ W, const float* __restrict__ V,
                         __half* __restrict__ hi, __half* __restrict__ lo)
{
    const int row = blockIdx.x;           // 0 .. NL*512-1
    const int l = row >> 9, k = row & 511;
    const int n = threadIdx.x * 4;        // 256 threads -> 1024 cols
    const float* src = (n < 512) ? (W + ((size_t)l * DD + k) * DD + n)
                                 : (V + ((size_t)l * DD + k) * DD + n - 512);
    float4 v = *reinterpret_cast<const float4*>(src);
    __half h0 = __float2half_rn(v.x), h1 = __float2half_rn(v.y);
    __half h2 = __float2half_rn(v.z), h3 = __float2half_rn(v.w);
    const size_t o = (size_t)row * 1024 + n;
    *reinterpret_cast<__half2*>(hi + o)     = __halves2half2(h0, h1);
    *reinterpret_cast<__half2*>(hi + o + 2) = __halves2half2(h2, h3);
    *reinterpret_cast<__half2*>(lo + o) = __halves2half2(
        __float2half_rn(v.x - __half2float(h0)),
        __float2half_rn(v.y - __half2float(h1)));
    *reinterpret_cast<__half2*>(lo + o + 2) = __halves2half2(
        __float2half_rn(v.z - __half2float(h2)),
        __float2half_rn(v.w - __half2float(h3)));
}

// ---------------------------------------------------------------------------
// Column degrees
// ---------------------------------------------------------------------------
__global__ void colsum_part_k(const float* __restrict__ A, float* __restrict__ part)
{
    int s = blockIdx.x * blockDim.x + threadIdx.x;
    if (s >= NS) return;
    int chunk = blockIdx.y;
    const int rows = NR / COL_CHUNKS;
    const float* p = A + (size_t)(chunk * rows) * NS + s;
    float acc = 0.f;
    for (int r = 0; r < rows; r++) acc += p[(size_t)r * NS];
    part[chunk * NS + s] = acc;
}
__global__ void colsum_fin_k(const float* __restrict__ part, float* __restrict__ invdeg)
{
    int s = blockIdx.x * blockDim.x + threadIdx.x;
    if (s >= NS) return;
    float acc = 0.f;
    #pragma unroll
    for (int c = 0; c < COL_CHUNKS; c++) acc += part[c * NS + s];
    invdeg[s] = 1.f / (acc + 1e-6f);
}

// ---------------------------------------------------------------------------
// Host orchestration
// ---------------------------------------------------------------------------
extern "C" void kernel_launch(void* const* d_in, const int* in_sizes, int n_in,
                              void* d_out, int out_size)
{
    const float* h_s_in = (const float*)d_in[0];  // [NS, DD]
    const float* A      = (const float*)d_in[1];  // [NR, NS]
    const float* r_emb  = (const float*)d_in[2];  // [NR, DD]
    const float* Wr     = (const float*)d_in[3];  // [NL, DD, DD]
    const float* Ws     = (const float*)d_in[4];
    const float* Vr     = (const float*)d_in[5];
    const float* Vs     = (const float*)d_in[6];
    float* out = (float*)d_out;                   // [NR, DD]

    cudaFuncSetAttribute(hmma_gemm_k<0, 1, 1>,
                         cudaFuncAttributeMaxDynamicSharedMemorySize, SMEM_SPLIT);
    cudaFuncSetAttribute(hmma_gemm_k<0, 0, 0>,
                         cudaFuncAttributeMaxDynamicSharedMemorySize, SMEM_1TERM);
    cudaFuncSetAttribute(hmma_gemm_k<1, 0, 0>,
                         cudaFuncAttributeMaxDynamicSharedMemorySize, SMEM_1TERM);

    float *invdr, *invds, *colpart, *fS, *fR, *partR, *partS;
    __half *Ahi, *hrhi, *hrlo, *hshi, *hslo, *gshi, *grhi;
    __half *WShi, *WSlo, *WRhi, *WRlo;
    cudaGetSymbolAddress((void**)&invdr,   g_invdeg_r);
    cudaGetSymbolAddress((void**)&invds,   g_invdeg_s);
    cudaGetSymbolAddress((void**)&colpart, g_colpart);
    cudaGetSymbolAddress((void**)&fS,    g_fS);
    cudaGetSymbolAddress((void**)&fR,    g_fR);
    cudaGetSymbolAddress((void**)&partR, g_partR);
    cudaGetSymbolAddress((void**)&partS, g_partS);
    cudaGetSymbolAddress((void**)&Ahi,  g_Ahi);
    cudaGetSymbolAddress((void**)&hrhi, g_hrhi);
    cudaGetSymbolAddress((void**)&hrlo, g_hrlo);
    cudaGetSymbolAddress((void**)&hshi, g_hshi);
    cudaGetSymbolAddress((void**)&hslo, g_hslo);
    cudaGetSymbolAddress((void**)&gshi, g_gshi);
    cudaGetSymbolAddress((void**)&grhi, g_grhi);
    cudaGetSymbolAddress((void**)&WShi, g_WShi);
    cudaGetSymbolAddress((void**)&WSlo, g_WSlo);
    cudaGetSymbolAddress((void**)&WRhi, g_WRhi);
    cudaGetSymbolAddress((void**)&WRlo, g_WRlo);

    split_cols_k<<<NS_P, 128>>>(h_s_in, DD, 0, hshi, hslo, NS);
    splitW_k<<<NL * DD, 256>>>(Ws, Vs, WShi, WSlo);
    splitW_k<<<NL * DD, 256>>>(Wr, Vr, WRhi, WRlo);

    for (int l = 0; l < NL; l++) {
        const bool last = (l == NL - 1);
        const int NW = last ? 512 : 1024;

        // fS = h_s @ [Ws|Vs][l]   -> fp32 [NS, 1024]   (3-term split)
        hmma_gemm_k<0, 1, 1><<<dim3(NW / 128, NS_P / 128, 1), 256, SMEM_SPLIT>>>(
            NS, DD / 32, hshi, hslo, DD,
            WShi + (size_t)l * DD * 1024, WSlo + (size_t)l * DD * 1024, 1024,
            fS, 1024, 0);

        if (l == 0) {
            split_cols_k<<<NR_P, 128>>>(r_emb, DD, 0, hrhi, hrlo, NR);
            splitA_hi_k<<<NR_P, 256>>>(A, Ahi, invdr);
            colsum_part_k<<<dim3((NS + 255) / 256, COL_CHUNKS), 256>>>(A, colpart);
            colsum_fin_k<<<(NS + 255) / 256, 256>>>(colpart, invds);
        }

        // fR = h_r @ [Wr|Vr][l]   -> fp32 [NR, 1024]   (3-term split)
        hmma_gemm_k<0, 1, 1><<<dim3(NW / 128, NR_P / 128, 1), 256, SMEM_SPLIT>>>(
            NR, DD / 32, hrhi, hrlo, DD,
            WRhi + (size_t)l * DD * 1024, WRlo + (size_t)l * DD * 1024, 1024,
            fR, 1024, 0);

        // gs -> fp16 hi only (big GEMM is 1-term; aggregation is deg-diluted)
        split_cols_hi_k<<<NS_P, 128>>>(fS, 1024, 0, gshi, NS);

        // h_r' = relu(invdeg_r * (A @ gs) + tr), pure fp16, split-K
        hmma_gemm_k<0, 0, 0><<<dim3(4, NR_P / 128, KSPLIT_R), 256, SMEM_1TERM>>>(
            NR, NS_P / 32, Ahi, nullptr, NS_P, gshi, nullptr, DD,
            partR, DD, (size_t)NR * DD);
        if (last) {
            reduce_epi_k<1><<<(NR * 128 + 255) / 256, 256>>>(
                NR, NR, KSPLIT_R, partR, (size_t)NR * DD, invdr, fR, 1024,
                out, nullptr, nullptr);
        } else {
            reduce_epi_k<0><<<(NR_P * 128 + 255) / 256, 256>>>(
                NR, NR_P, KSPLIT_R, partR, (size_t)NR * DD, invdr, fR, 1024,
                nullptr, hrhi, hrlo);

            // gr -> fp16 hi only
            split_cols_hi_k<<<NR_P, 128>>>(fR, 1024, 512, grhi, NR);

            // h_s' = relu(invdeg_s * (A^T @ gr) + ts), pure fp16, A transposed
            hmma_gemm_k<1, 0, 0><<<dim3(4, NS_P / 128, KSPLIT_S), 256, SMEM_1TERM>>>(
                NS, KR_P / 32, Ahi, nullptr, NS_P, grhi, nullptr, DD,
                partS, DD, (size_t)NS * DD);
            reduce_epi_k<0><<<(NS_P * 128 + 255) / 256, 256>>>(
                NS, NS_P, KSPLIT_S, partS, (size_t)NS * DD, invds, fS + 512, 1024,
                nullptr, hshi, hslo);
        }
    }
}

// round 12
// speedup vs baseline: 8.3082x; 1.0717x over previous
#include <cuda_runtime.h>
#include <cuda_fp16.h>
#include <cstdint>

// ---------------------------------------------------------------------------
// Problem constants
// ---------------------------------------------------------------------------
#define NR 20000          // readings
#define NS 5000           // skills
#define DD 512            // embedding dim
#define NL 3              // layers
#define NR_P 20096        // NR padded to 128
#define NS_P 5120         // NS padded to 128
#define KR_P 20032        // NR padded to 64 (K dim of A^T GEMM)
#define COL_CHUNKS 16
#define KSPLIT_R 4        // split-K for A@gs   (grid 4*157*4 = 2512)
#define KSPLIT_S 16       // split-K for A^T@gr (grid 4*40*16 = 2560)

// ---------------------------------------------------------------------------
// Device scratch (no cudaMalloc allowed)
// ---------------------------------------------------------------------------
__device__ float g_invdeg_r[NR];
__device__ float g_invdeg_s[NS];
__device__ float g_colpart[COL_CHUNKS * NS];

__device__ __align__(16) __half g_Ahi[(size_t)NR_P * NS_P];
__device__ __align__(16) __half g_hrhi[(size_t)NR_P * DD];
__device__ __align__(16) __half g_hrlo[(size_t)NR_P * DD];
__device__ __align__(16) __half g_hshi[(size_t)NS_P * DD];
__device__ __align__(16) __half g_gshi[(size_t)NS_P * DD];
__device__ __align__(16) __half g_grhi[(size_t)NR_P * DD];
__device__ __align__(16) __half g_WShi[(size_t)NL * DD * 1024];  // [Ws|Vs] hi
__device__ __align__(16) __half g_Wrhi[(size_t)NL * DD * DD];
__device__ __align__(16) __half g_Wrlo[(size_t)NL * DD * DD];
__device__ __align__(16) __half g_Vrhi[(size_t)NL * DD * DD];

__device__ float g_fS[(size_t)NS * 1024];            // [gs | ts]
__device__ float g_tr[(size_t)NR * DD];
__device__ float g_partR[(size_t)KSPLIT_R * NR * DD];
__device__ float g_partS[(size_t)KSPLIT_S * NS * DD];

// ---------------------------------------------------------------------------
// PTX helpers (Ampere-era ISA: compiles for plain compute_103 target)
// ---------------------------------------------------------------------------
__device__ __forceinline__ uint32_t smem_u32(const void* p) {
    uint32_t a;
    asm("{ .reg .u64 t; cvta.to.shared.u64 t, %1; cvt.u32.u64 %0, t; }"
        : "=r"(a) : "l"(p));
    return a;
}
__device__ __forceinline__ void cp16(uint32_t dst, const void* src) {
    asm volatile("cp.async.cg.shared.global [%0], [%1], 16;"
                 :: "r"(dst), "l"(src) : "memory");
}
__device__ __forceinline__ void cp_commit() {
    asm volatile("cp.async.commit_group;" ::: "memory");
}
template <int N>
__device__ __forceinline__ void cp_wait() {
    asm volatile("cp.async.wait_group %0;" :: "n"(N) : "memory");
}
__device__ __forceinline__ void ldsm4(uint32_t& r0, uint32_t& r1,
                                      uint32_t& r2, uint32_t& r3, uint32_t a) {
    asm volatile("ldmatrix.sync.aligned.m8n8.x4.shared.b16 {%0,%1,%2,%3}, [%4];"
                 : "=r"(r0), "=r"(r1), "=r"(r2), "=r"(r3) : "r"(a));
}
__device__ __forceinline__ void ldsm4t(uint32_t& r0, uint32_t& r1,
                                       uint32_t& r2, uint32_t& r3, uint32_t a) {
    asm volatile("ldmatrix.sync.aligned.m8n8.x4.trans.shared.b16 {%0,%1,%2,%3}, [%4];"
                 : "=r"(r0), "=r"(r1), "=r"(r2), "=r"(r3) : "r"(a));
}
__device__ __forceinline__ void mma16816(float* d, const uint32_t* a,
                                         const uint32_t* b) {
    asm volatile(
        "mma.sync.aligned.m16n8k16.row.col.f32.f16.f16.f32 "
        "{%0,%1,%2,%3}, {%4,%5,%6,%7}, {%8,%9}, {%0,%1,%2,%3};"
        : "+f"(d[0]), "+f"(d[1]), "+f"(d[2]), "+f"(d[3])
        : "r"(a[0]), "r"(a[1]), "r"(a[2]), "r"(a[3]), "r"(b[0]), "r"(b[1]));
}
// A-normal tile [128m x BKk] (BK/8 segments of 2KB). MUL=2 for BK32 (store
// phase = 2 rows x 4 chunks), MUL=1 for BK64 (phase = 1 row x 8 chunks).
__device__ __forceinline__ uint32_t swzA(int r, int c16, int mul) {
    return (uint32_t)((c16 << 11) + ((r >> 3) << 7) + (((r + mul * c16) & 7) << 4));
}
// K-major tile [BKk x 128cols] (256B rows): XOR swizzle, conflict-free for
// cp.async stores and ldmatrix phases.
__device__ __forceinline__ uint32_t swz_kn(int r, int c) {
    return (uint32_t)(r * 256 + ((c & 8) << 4) + (((c ^ r) & 7) << 4));
}

// ---------------------------------------------------------------------------
// Stage loader. Layout: Ahi(+0) [Alo(+AHALF)] Bhi(+BOFF) [Blo(+BOFF+BHALF)]
// ---------------------------------------------------------------------------
template <int A_TRANS, int A_SPLIT, int B_SPLIT, int BK64>
__device__ __forceinline__ void load_stage(uint32_t sb,
    const __half* __restrict__ Ahi, const __half* __restrict__ Alo,
    int lda, int bm,
    const __half* __restrict__ Bhi, const __half* __restrict__ Blo,
    int ldb, int bn, int k0, int tid)
{
    constexpr uint32_t HALF = BK64 ? 16384u : 8192u;
    constexpr uint32_t BOFF = HALF * (1 + A_SPLIT);
    constexpr int ITER = BK64 ? 4 : 2;
    constexpr int CMASK = BK64 ? 7 : 3;
    constexpr int CSH   = BK64 ? 3 : 2;
    constexpr int MUL   = BK64 ? 1 : 2;
    #pragma unroll
    for (int i = 0; i < ITER; i++) {
        const int idx = tid + i * 256;
        const int r = idx >> 4, c = idx & 15;
        const uint32_t so = swz_kn(r, c);
        const size_t bo = (size_t)(k0 + r) * ldb + bn + c * 8;
        cp16(sb + BOFF + so, Bhi + bo);
        if (B_SPLIT) cp16(sb + BOFF + HALF + so, Blo + bo);
        if (A_TRANS) {
            const size_t ao = (size_t)(k0 + r) * lda + bm + c * 8;
            cp16(sb + so, Ahi + ao);
            if (A_SPLIT) cp16(sb + HALF + so, Alo + ao);
        } else {
            const int c16 = idx & CMASK, ra = idx >> CSH;
            const uint32_t soA = swzA(ra, c16, MUL);
            const size_t ao = (size_t)(bm + ra) * lda + k0 + c16 * 8;
            cp16(sb + soA, Ahi + ao);
            if (A_SPLIT) cp16(sb + HALF + soA, Alo + ao);
        }
    }
}

// ---------------------------------------------------------------------------
// HMMA GEMM: C[M,N] = op(A)[M,K] @ B[K,N]
//   Split-product terms kept: Ah*Bh (+Ah*Bl if B_SPLIT) (+Al*Bh if A_SPLIT).
//   A_TRANS=1 reads A from [K,M] row-major. BK64: 64-wide K chunks.
//   OUT_HALF=1: write fp16 results (C interpreted as __half*).
//   CTA 128x128, 3-stage cp.async, 8 warps as 2M x 4N, 2 CTAs/SM.
//   Split-K over gridDim.z -> plain partials at C + z*part_stride.
// ---------------------------------------------------------------------------
template <int A_TRANS, int A_SPLIT, int B_SPLIT, int BK64, int OUT_HALF>
__global__ void __launch_bounds__(256, 2)
hmma_gemm_k(int M, int Kc,
            const __half* __restrict__ Ahi, const __half* __restrict__ Alo,
            int lda,
            const __half* __restrict__ Bhi, const __half* __restrict__ Blo,
            int ldb,
            void* __restrict__ Cv, int ldc, size_t part_stride)
{
    constexpr uint32_t HALF = BK64 ? 16384u : 8192u;
    constexpr uint32_t BOFF = HALF * (1 + A_SPLIT);
    constexpr int STAGE = (int)HALF * (2 + A_SPLIT + B_SPLIT);
    constexpr int NST   = 3;
    constexpr int KSUB  = BK64 ? 4 : 2;
    constexpr int KW    = BK64 ? 64 : 32;
    constexpr int MUL   = BK64 ? 1 : 2;

    extern __shared__ char sm[];
    const uint32_t smb = smem_u32(sm);
    const int tid  = threadIdx.x;
    const int wid  = tid >> 5;
    const int lane = tid & 31;
    const int warp_m = wid & 1;    // 0..1 (64 rows each)
    const int warp_n = wid >> 1;   // 0..3 (32 cols each)
    const int bm = blockIdx.y * 128;
    const int bn = blockIdx.x * 128;

    const int P = gridDim.z, p = blockIdx.z;
    const int kbase = Kc / P, krem = Kc - kbase * P;
    const int kc0 = p * kbase + (p < krem ? p : krem);
    const int kcn = kbase + (p < krem ? 1 : 0);

    float acc[4][4][4];
    #pragma unroll
    for (int mf = 0; mf < 4; mf++)
        #pragma unroll
        for (int nt = 0; nt < 4; nt++)
            #pragma unroll
            for (int i = 0; i < 4; i++) acc[mf][nt][i] = 0.f;

    #pragma unroll
    for (int s = 0; s < NST - 1; s++) {
        if (s < kcn)
            load_stage<A_TRANS, A_SPLIT, B_SPLIT, BK64>(
                smb + s * STAGE, Ahi, Alo, lda, bm,
                Bhi, Blo, ldb, bn, (kc0 + s) * KW, tid);
        cp_commit();
    }

    // per-lane ldmatrix indices
    const int aN_r  = warp_m * 64 + (lane & 15);        // A normal: m row
    const int aN_ch = lane >> 4;                         // A normal: k chunk
    const int aT_r  = (lane & 7) + ((lane >> 4) << 3);   // A trans: k row off
    const int aT_cb = warp_m * 8 + ((lane >> 3) & 1);    // A trans: m chunk
    const int b_r   = lane & 15;                         // B: k row offset
    const int b_cb  = warp_n * 4 + (lane >> 4);          // B: n chunk base

    for (int ci = 0; ci < kcn; ci++) {
        cp_wait<NST - 2>();
        __syncthreads();
        if (ci + NST - 1 < kcn)
            load_stage<A_TRANS, A_SPLIT, B_SPLIT, BK64>(
                smb + ((ci + NST - 1) % NST) * STAGE, Ahi, Alo, lda, bm,
                Bhi, Blo, ldb, bn, (kc0 + ci + NST - 1) * KW, tid);
        cp_commit();

        const uint32_t sb = smb + (ci % NST) * STAGE;
        #pragma unroll
        for (int ks = 0; ks < KSUB; ks++) {
            uint32_t ah[4][4], al[4][4], bh[2][4], bl[2][4];
            #pragma unroll
            for (int mf = 0; mf < 4; mf++) {
                if (A_TRANS) {
                    const uint32_t ad =
                        sb + swz_kn(ks * 16 + aT_r, aT_cb + mf * 2);
                    ldsm4t(ah[mf][0], ah[mf][1], ah[mf][2], ah[mf][3], ad);
                    if (A_SPLIT)
                        ldsm4t(al[mf][0], al[mf][1], al[mf][2], al[mf][3],
                               ad + HALF);
                } else {
                    const uint32_t ad =
                        sb + swzA(aN_r + mf * 16, ks * 2 + aN_ch, MUL);
                    ldsm4(ah[mf][0], ah[mf][1], ah[mf][2], ah[mf][3], ad);
                    if (A_SPLIT)
                        ldsm4(al[mf][0], al[mf][1], al[mf][2], al[mf][3],
                              ad + HALF);
                }
            }
            #pragma unroll
            for (int np = 0; np < 2; np++) {
                const uint32_t bd =
                    sb + BOFF + swz_kn(ks * 16 + b_r, b_cb + np * 2);
                ldsm4t(bh[np][0], bh[np][1], bh[np][2], bh[np][3], bd);
                if (B_SPLIT)
                    ldsm4t(bl[np][0], bl[np][1], bl[np][2], bl[np][3],
                           bd + HALF);
            }
            #pragma unroll
            for (int mf = 0; mf < 4; mf++) {
                #pragma unroll
                for (int np = 0; np < 2; np++) {
                    mma16816(acc[mf][np * 2],     ah[mf], &bh[np][0]);
                    mma16816(acc[mf][np * 2 + 1], ah[mf], &bh[np][2]);
                    if (B_SPLIT) {
                        mma16816(acc[mf][np * 2],     ah[mf], &bl[np][0]);
                        mma16816(acc[mf][np * 2 + 1], ah[mf], &bl[np][2]);
                    }
                    if (A_SPLIT) {
                        mma16816(acc[mf][np * 2],     al[mf], &bh[np][0]);
                        mma16816(acc[mf][np * 2 + 1], al[mf], &bh[np][2]);
                    }
                }
            }
        }
    }

    const int row_in = lane >> 2;
    const int col_in = (lane & 3) * 2;
    #pragma unroll
    for (int mf = 0; mf < 4; mf++) {
        #pragma unroll
        for (int h2 = 0; h2 < 2; h2++) {
            const int m = bm + warp_m * 64 + mf * 16 + row_in + h2 * 8;
            if (m >= M) continue;
            #pragma unroll
            for (int nt = 0; nt < 4; nt++) {
                const int n = bn + warp_n * 32 + nt * 8 + col_in;
                const float v0 = acc[mf][nt][h2 * 2 + 0];
                const float v1 = acc[mf][nt][h2 * 2 + 1];
                if (OUT_HALF) {
                    __half* C = (__half*)Cv + part_stride * (size_t)p;
                    *reinterpret_cast<__half2*>(C + (size_t)m * ldc + n) =
                        __halves2half2(__float2half_rn(v0), __float2half_rn(v1));
                } else {
                    float* C = (float*)Cv + part_stride * (size_t)p;
                    float2 o; o.x = v0; o.y = v1;
                    *reinterpret_cast<float2*>(C + (size_t)m * ldc + n) = o;
                }
            }
        }
    }
}

#define SMEM_3TERM (3 * 32768)   // BK32 3-term
#define SMEM_1T64  (3 * 32768)   // BK64 1-term

// ---------------------------------------------------------------------------
// reduce + epilogue: v = relu(invdeg[m] * sum_p part[p] + add[m,n])
//   MODE 0: fp32 out (rows < M). MODE 1: fp16 hi+lo (padded rows zero).
//   MODE 2: fp16 hi only (padded rows zero).
// ---------------------------------------------------------------------------
template <int MODE>
__global__ void reduce_epi_k(int M, int MP, int P,
                             const float* __restrict__ part, size_t pstride,
                             const float* __restrict__ invdeg,
                             const float* __restrict__ add, int ld_add,
                             float* __restrict__ out32,
                             __half* __restrict__ hi, __half* __restrict__ lo)
{
    int idx = blockIdx.x * 256 + threadIdx.x;   // over MP * 128 float4s
    if (idx >= MP * 128) return;
    int m = idx >> 7, q = (idx & 127) << 2;
    float4 o = make_float4(0.f, 0.f, 0.f, 0.f);
    if (m < M) {
        float4 s = make_float4(0.f, 0.f, 0.f, 0.f);
        for (int pp = 0; pp < P; pp++) {
            const float4 v = *reinterpret_cast<const float4*>(
                part + pp * pstride + (size_t)m * DD + q);
            s.x += v.x; s.y += v.y; s.z += v.z; s.w += v.w;
        }
        const float sc = invdeg[m];
        const float4 a = *reinterpret_cast<const float4*>(
            add + (size_t)m * ld_add + q);
        o.x = fmaxf(fmaf(sc, s.x, a.x), 0.f);
        o.y = fmaxf(fmaf(sc, s.y, a.y), 0.f);
        o.z = fmaxf(fmaf(sc, s.z, a.z), 0.f);
        o.w = fmaxf(fmaf(sc, s.w, a.w), 0.f);
    }
    if (MODE == 0) {
        if (m < M)
            *reinterpret_cast<float4*>(out32 + (size_t)m * DD + q) = o;
    } else {
        __half h0 = __float2half_rn(o.x), h1 = __float2half_rn(o.y);
        __half h2 = __float2half_rn(o.z), h3 = __float2half_rn(o.w);
        const size_t off = (size_t)m * DD + q;
        *reinterpret_cast<__half2*>(hi + off)     = __halves2half2(h0, h1);
        *reinterpret_cast<__half2*>(hi + off + 2) = __halves2half2(h2, h3);
        if (MODE == 1) {
            *reinterpret_cast<__half2*>(lo + off) = __halves2half2(
                __float2half_rn(o.x - __half2float(h0)),
                __float2half_rn(o.y - __half2float(h1)));
            *reinterpret_cast<__half2*>(lo + off + 2) = __halves2half2(
                __float2half_rn(o.z - __half2float(h2)),
                __float2half_rn(o.w - __half2float(h3)));
        }
    }
}

// ---------------------------------------------------------------------------
// Conversions
// ---------------------------------------------------------------------------
// A [NR x 5000] fp32 -> hi [NR_P x NS_P] fp16, fused with row degrees.
__global__ void splitA_hi_k(const float* __restrict__ A,
                            __half* __restrict__ hi,
                            float* __restrict__ invdeg)
{
    const int r = blockIdx.x;           // 0..NR_P-1
    const bool real = (r < NR);
    const int tid = threadIdx.x;        // 256
    float acc = 0.f;
    for (int c4 = tid; c4 < NS_P / 4; c4 += 256) {
        float4 v = make_float4(0.f, 0.f, 0.f, 0.f);
        if (real && c4 < NS / 4)
            v = *reinterpret_cast<const float4*>(A + (size_t)r * NS + c4 * 4);
        acc += (v.x + v.y) + (v.z + v.w);
        const size_t o = (size_t)r * NS_P + c4 * 4;
        *reinterpret_cast<__half2*>(hi + o) =
            __halves2half2(__float2half_rn(v.x), __float2half_rn(v.y));
        *reinterpret_cast<__half2*>(hi + o + 2) =
            __halves2half2(__float2half_rn(v.z), __float2half_rn(v.w));
    }
    #pragma unroll
    for (int off = 16; off; off >>= 1) acc += __shfl_down_sync(0xffffffffu, acc, off);
    __shared__ float ws[8];
    if ((tid & 31) == 0) ws[tid >> 5] = acc;
    __syncthreads();
    if (tid == 0 && real) {
        float s = 0.f;
        #pragma unroll
        for (int w = 0; w < 8; w++) s += ws[w];
        invdeg[r] = 1.f / (s + 1e-6f);
    }
}

// fp32 cols [col0,col0+512) of [M x ld] -> fp16 hi/lo [grid x 512] zero-pad.
__global__ void split_cols_k(const float* __restrict__ in, int ld, int col0,
                             __half* __restrict__ hi, __half* __restrict__ lo,
                             int M)
{
    const int r = blockIdx.x;
    const int c = threadIdx.x * 4;
    float4 v = make_float4(0.f, 0.f, 0.f, 0.f);
    if (r < M)
        v = *reinterpret_cast<const float4*>(in + (size_t)r * ld + col0 + c);
    __half h0 = __float2half_rn(v.x), h1 = __float2half_rn(v.y);
    __half h2 = __float2half_rn(v.z), h3 = __float2half_rn(v.w);
    const size_t o = (size_t)r * DD + c;
    *reinterpret_cast<__half2*>(hi + o)     = __halves2half2(h0, h1);
    *reinterpret_cast<__half2*>(hi + o + 2) = __halves2half2(h2, h3);
    *reinterpret_cast<__half2*>(lo + o) = __halves2half2(
        __float2half_rn(v.x - __half2float(h0)),
        __float2half_rn(v.y - __half2float(h1)));
    *reinterpret_cast<__half2*>(lo + o + 2) = __halves2half2(
        __float2half_rn(v.z - __half2float(h2)),
        __float2half_rn(v.w - __half2float(h3)));
}

// fp32 cols [col0,col0+512) -> fp16 hi ONLY, [grid x 512] zero-padded.
__global__ void split_cols_hi_k(const float* __restrict__ in, int ld, int col0,
                                __half* __restrict__ hi, int M)
{
    const int r = blockIdx.x;
    const int c = threadIdx.x * 4;
    float4 v = make_float4(0.f, 0.f, 0.f, 0.f);
    if (r < M)
        v = *reinterpret_cast<const float4*>(in + (size_t)r * ld + col0 + c);
    const size_t o = (size_t)r * DD + c;
    *reinterpret_cast<__half2*>(hi + o) =
        __halves2half2(__float2half_rn(v.x), __float2half_rn(v.y));
    *reinterpret_cast<__half2*>(hi + o + 2) =
        __halves2half2(__float2half_rn(v.z), __float2half_rn(v.w));
}

// Build combined [W|V] fp16 hi for all NL layers: out [NL*512 x 1024].
__global__ void splitW_hi_k(const float* __restrict__ W,
                            const float* __restrict__ V,
                            __half* __restrict__ hi)
{
    const int row = blockIdx.x;           // 0 .. NL*512-1
    const int l = row >> 9, k = row & 511;
    const int n = threadIdx.x * 4;        // 256 threads -> 1024 cols
    const float* src = (n < 512) ? (W + ((size_t)l * DD + k) * DD + n)
                                 : (V + ((size_t)l * DD + k) * DD + n - 512);
    float4 v = *reinterpret_cast<const float4*>(src);
    const size_t o = (size_t)row * 1024 + n;
    *reinterpret_cast<__half2*>(hi + o) =
        __halves2half2(__float2half_rn(v.x), __float2half_rn(v.y));
    *reinterpret_cast<__half2*>(hi + o + 2) =
        __halves2half2(__float2half_rn(v.z), __float2half_rn(v.w));
}

// ---------------------------------------------------------------------------
// Column degrees
// ---------------------------------------------------------------------------
__global__ void colsum_part_k(const float* __restrict__ A, float* __restrict__ part)
{
    int s = blockIdx.x * blockDim.x + threadIdx.x;
    if (s >= NS) return;
    int chunk = blockIdx.y;
    const int rows = NR / COL_CHUNKS;
    const float* p = A + (size_t)(chunk * rows) * NS + s;
    float acc = 0.f;
    for (int r = 0; r < rows; r++) acc += p[(size_t)r * NS];
    part[chunk * NS + s] = acc;
}
__global__ void colsum_fin_k(const float* __restrict__ part, float* __restrict__ invdeg)
{
    int s = blockIdx.x * blockDim.x + threadIdx.x;
    if (s >= NS) return;
    float acc = 0.f;
    #pragma unroll
    for (int c = 0; c < COL_CHUNKS; c++) acc += part[c * NS + s];
    invdeg[s] = 1.f / (acc + 1e-6f);
}

// ---------------------------------------------------------------------------
// Host orchestration
// ---------------------------------------------------------------------------
extern "C" void kernel_launch(void* const* d_in, const int* in_sizes, int n_in,
                              void* d_out, int out_size)
{
    const float* h_s_in = (const float*)d_in[0];  // [NS, DD]
    const float* A      = (const float*)d_in[1];  // [NR, NS]
    const float* r_emb  = (const float*)d_in[2];  // [NR, DD]
    const float* Wr     = (const float*)d_in[3];  // [NL, DD, DD]
    const float* Ws     = (const float*)d_in[4];
    const float* Vr     = (const float*)d_in[5];
    const float* Vs     = (const float*)d_in[6];
    float* out = (float*)d_out;                   // [NR, DD]

    cudaFuncSetAttribute((const void*)hmma_gemm_k<0, 1, 1, 0, 0>,
                         cudaFuncAttributeMaxDynamicSharedMemorySize, SMEM_3TERM);
    cudaFuncSetAttribute((const void*)hmma_gemm_k<0, 0, 0, 1, 0>,
                         cudaFuncAttributeMaxDynamicSharedMemorySize, SMEM_1T64);
    cudaFuncSetAttribute((const void*)hmma_gemm_k<0, 0, 0, 1, 1>,
                         cudaFuncAttributeMaxDynamicSharedMemorySize, SMEM_1T64);
    cudaFuncSetAttribute((const void*)hmma_gemm_k<1, 0, 0, 1, 0>,
                         cudaFuncAttributeMaxDynamicSharedMemorySize, SMEM_1T64);

    float *invdr, *invds, *colpart, *fS, *tr, *partR, *partS;
    __half *Ahi, *hrhi, *hrlo, *hshi, *gshi, *grhi, *WShi, *Wrhi, *Wrlo, *Vrhi;
    cudaGetSymbolAddress((void**)&invdr,   g_invdeg_r);
    cudaGetSymbolAddress((void**)&invds,   g_invdeg_s);
    cudaGetSymbolAddress((void**)&colpart, g_colpart);
    cudaGetSymbolAddress((void**)&fS,    g_fS);
    cudaGetSymbolAddress((void**)&tr,    g_tr);
    cudaGetSymbolAddress((void**)&partR, g_partR);
    cudaGetSymbolAddress((void**)&partS, g_partS);
    cudaGetSymbolAddress((void**)&Ahi,  g_Ahi);
    cudaGetSymbolAddress((void**)&hrhi, g_hrhi);
    cudaGetSymbolAddress((void**)&hrlo, g_hrlo);
    cudaGetSymbolAddress((void**)&hshi, g_hshi);
    cudaGetSymbolAddress((void**)&gshi, g_gshi);
    cudaGetSymbolAddress((void**)&grhi, g_grhi);
    cudaGetSymbolAddress((void**)&WShi, g_WShi);
    cudaGetSymbolAddress((void**)&Wrhi, g_Wrhi);
    cudaGetSymbolAddress((void**)&Wrlo, g_Wrlo);
    cudaGetSymbolAddress((void**)&Vrhi, g_Vrhi);

    // 1: h_s hi split  2: [Ws|Vs] hi  3: Wr hi/lo  4: fS GEMM (profiled)
    split_cols_hi_k<<<NS_P, 128>>>(h_s_in, DD, 0, hshi, NS);
    splitW_hi_k<<<NL * DD, 256>>>(Ws, Vs, WShi);
    split_cols_k<<<NL * DD, 128>>>(Wr, DD, 0, Wrhi, Wrlo, NL * DD);

    for (int l = 0; l < NL; l++) {
        const bool last = (l == NL - 1);
        const int NW = last ? 512 : 1024;

        // fS = h_s @ [Ws|Vs][l] -> fp32 [NS, 1024]   (1-term, BK64)
        hmma_gemm_k<0, 0, 0, 1, 0><<<dim3(NW / 128, NS_P / 128, 1), 256, SMEM_1T64>>>(
            NS, DD / 64, hshi, nullptr, DD,
            WShi + (size_t)l * DD * 1024, nullptr, 1024, fS, 1024, 0);

        if (l == 0) {
            split_cols_hi_k<<<NL * DD, 128>>>(Vr, DD, 0, Vrhi, NL * DD);
            split_cols_k<<<NR_P, 128>>>(r_emb, DD, 0, hrhi, hrlo, NR);
            splitA_hi_k<<<NR_P, 256>>>(A, Ahi, invdr);
            colsum_part_k<<<dim3((NS + 255) / 256, COL_CHUNKS), 256>>>(A, colpart);
            colsum_fin_k<<<(NS + 255) / 256, 256>>>(colpart, invds);
        }

        // tr = h_r @ Wr[l] -> fp32 [NR, 512]   (3-term, precision-critical)
        hmma_gemm_k<0, 1, 1, 0, 0><<<dim3(4, NR_P / 128, 1), 256, SMEM_3TERM>>>(
            NR, DD / 32, hrhi, hrlo, DD,
            Wrhi + (size_t)l * DD * DD, Wrlo + (size_t)l * DD * DD, DD,
            tr, DD, 0);

        // gs -> fp16 hi (aggregation operand, deg-diluted)
        split_cols_hi_k<<<NS_P, 128>>>(fS, 1024, 0, gshi, NS);

        // big: partR = A @ gs (1-term, BK64, split-K)
        hmma_gemm_k<0, 0, 0, 1, 0><<<dim3(4, NR_P / 128, KSPLIT_R), 256, SMEM_1T64>>>(
            NR, NS_P / 64, Ahi, nullptr, NS_P, gshi, nullptr, DD,
            partR, DD, (size_t)NR * DD);

        if (!last) {
            // gr = h_r @ Vr[l] -> fp16 direct (uses OLD h_r; before reduceR)
            hmma_gemm_k<0, 0, 0, 1, 1><<<dim3(4, NR_P / 128, 1), 256, SMEM_1T64>>>(
                NR_P, DD / 64, hrhi, nullptr, DD,
                Vrhi + (size_t)l * DD * DD, nullptr, DD, grhi, DD, 0);
        }

        // h_r' = relu(invdeg_r * (A @ gs) + tr)
        if (last) {
            reduce_epi_k<0><<<(NR * 128 + 255) / 256, 256>>>(
                NR, NR, KSPLIT_R, partR, (size_t)NR * DD, invdr, tr, DD,
                out, nullptr, nullptr);
        } else {
            reduce_epi_k<1><<<(NR_P * 128 + 255) / 256, 256>>>(
                NR, NR_P, KSPLIT_R, partR, (size_t)NR * DD, invdr, tr, DD,
                nullptr, hrhi, hrlo);

            // big: partS = A^T @ gr (1-term, BK64, A read transposed)
            hmma_gemm_k<1, 0, 0, 1, 0><<<dim3(4, NS_P / 128, KSPLIT_S), 256, SMEM_1T64>>>(
                NS, KR_P / 64, Ahi, nullptr, NS_P, grhi, nullptr, DD,
                partS, DD, (size_t)NS * DD);

            // h_s' = relu(invdeg_s * (A^T @ gr) + ts), hi-only
            reduce_epi_k<2><<<(NS_P * 128 + 255) / 256, 256>>>(
                NS, NS_P, KSPLIT_S, partS, (size_t)NS * DD, invds, fS + 512, 1024,
                nullptr, hshi, nullptr);
        }
    }
}